// round 1
// baseline (speedup 1.0000x reference)
#include <cuda_runtime.h>
#include <math.h>

// Problem constants
#define SEQ   4096
#define DIM   512
#define NH    8
#define HD    64
#define PAD   68        // smem row stride (floats): keeps float4 alignment, avoids conflicts

// Scratch (allocation-free rule: __device__ globals)
__device__ float g_Q[SEQ * DIM];
__device__ float g_K[SEQ * DIM];
__device__ float g_V[SEQ * DIM];
__device__ float g_ctx[SEQ * DIM];

// ---------------------------------------------------------------------------
// GEMM: C[M=4096][N=512] = X[M][K=512] @ W[N][K]^T + bias[N]
// 64x64 tile, 256 threads (16x16), 4x4 micro-tile per thread, BK=64.
// Smem holds both tiles transposed ([k][m] / [k][n]) so the inner loop does
// two float4 LDS (one broadcast-heavy) + 16 FMA per k.
// ---------------------------------------------------------------------------
__global__ __launch_bounds__(256) void gemm_bias_kernel(
    const float* __restrict__ X,
    const float* __restrict__ W,
    const float* __restrict__ bias,
    float* __restrict__ C)
{
    __shared__ float Xs[64 * PAD];
    __shared__ float Ws[64 * PAD];

    const int tx = threadIdx.x;          // 0..15 -> n micro
    const int ty = threadIdx.y;          // 0..15 -> m micro
    const int t  = ty * 16 + tx;
    const int m0 = blockIdx.y * 64;
    const int n0 = blockIdx.x * 64;

    const int lr = t & 63;               // row within tile for loading
    const int lk = (t >> 6) * 16;        // k segment (0,16,32,48)

    float acc[4][4] = {};

    for (int k0 = 0; k0 < DIM; k0 += 64) {
        #pragma unroll
        for (int i = 0; i < 4; i++) {
            int k = lk + i * 4;
            float4 xv = *(const float4*)&X[(m0 + lr) * DIM + k0 + k];
            Xs[(k + 0) * PAD + lr] = xv.x;
            Xs[(k + 1) * PAD + lr] = xv.y;
            Xs[(k + 2) * PAD + lr] = xv.z;
            Xs[(k + 3) * PAD + lr] = xv.w;
            float4 wv = *(const float4*)&W[(n0 + lr) * DIM + k0 + k];
            Ws[(k + 0) * PAD + lr] = wv.x;
            Ws[(k + 1) * PAD + lr] = wv.y;
            Ws[(k + 2) * PAD + lr] = wv.z;
            Ws[(k + 3) * PAD + lr] = wv.w;
        }
        __syncthreads();

        #pragma unroll 8
        for (int kk = 0; kk < 64; kk++) {
            float4 a = *(float4*)&Xs[kk * PAD + ty * 4];
            float4 b = *(float4*)&Ws[kk * PAD + tx * 4];
            acc[0][0] += a.x * b.x; acc[0][1] += a.x * b.y; acc[0][2] += a.x * b.z; acc[0][3] += a.x * b.w;
            acc[1][0] += a.y * b.x; acc[1][1] += a.y * b.y; acc[1][2] += a.y * b.z; acc[1][3] += a.y * b.w;
            acc[2][0] += a.z * b.x; acc[2][1] += a.z * b.y; acc[2][2] += a.z * b.z; acc[2][3] += a.z * b.w;
            acc[3][0] += a.w * b.x; acc[3][1] += a.w * b.y; acc[3][2] += a.w * b.z; acc[3][3] += a.w * b.w;
        }
        __syncthreads();
    }

    float4 bv = *(const float4*)&bias[n0 + tx * 4];
    #pragma unroll
    for (int i = 0; i < 4; i++) {
        float4 o;
        o.x = acc[i][0] + bv.x;
        o.y = acc[i][1] + bv.y;
        o.z = acc[i][2] + bv.z;
        o.w = acc[i][3] + bv.w;
        *(float4*)&C[(m0 + ty * 4 + i) * DIM + n0 + tx * 4] = o;
    }
}

// ---------------------------------------------------------------------------
// Flash-style attention. One block = one (q-tile of 64 rows) x (head).
// 256 threads (16x16), 4x4 micro-tiles. Online softmax in registers.
// Smem: Qs,Ks transposed [d][row]; Vs natural [kv][d]; Ps natural [row][kv].
// ---------------------------------------------------------------------------
__global__ __launch_bounds__(256) void attn_kernel()
{
    extern __shared__ float sm[];
    float* Qs = sm;                    // [64][PAD]  Qs[d][qrow] (pre-scaled)
    float* Ks = Qs + 64 * PAD;         // [64][PAD]  Ks[d][kvrow]
    float* Vs = Ks + 64 * PAD;         // [64][PAD]  Vs[kvrow][d]
    float* Ps = Vs + 64 * PAD;         // [64][PAD]  Ps[qrow][kvrow]

    const int tx = threadIdx.x;        // kv / head-dim micro index
    const int ty = threadIdx.y;        // q-row micro index
    const int t  = ty * 16 + tx;
    const int head = blockIdx.y;
    const int q0   = blockIdx.x * 64;

    const int lr = t & 63;
    const int lk = (t >> 6) * 16;

    // Load Q tile, transposed + pre-scaled by 1/sqrt(HD)
    const float scale = 0.125f;
    #pragma unroll
    for (int i = 0; i < 4; i++) {
        int k = lk + i * 4;
        float4 qv = *(const float4*)&g_Q[(q0 + lr) * DIM + head * HD + k];
        Qs[(k + 0) * PAD + lr] = qv.x * scale;
        Qs[(k + 1) * PAD + lr] = qv.y * scale;
        Qs[(k + 2) * PAD + lr] = qv.z * scale;
        Qs[(k + 3) * PAD + lr] = qv.w * scale;
    }

    float m_[4], l_[4], acc[4][4];
    #pragma unroll
    for (int i = 0; i < 4; i++) {
        m_[i] = -1e30f;
        l_[i] = 0.f;
        #pragma unroll
        for (int j = 0; j < 4; j++) acc[i][j] = 0.f;
    }

    for (int kv0 = 0; kv0 < SEQ; kv0 += 64) {
        __syncthreads();   // protect Ks/Vs/Ps from previous iteration readers
        #pragma unroll
        for (int i = 0; i < 4; i++) {
            int k = lk + i * 4;
            float4 kvv = *(const float4*)&g_K[(kv0 + lr) * DIM + head * HD + k];
            Ks[(k + 0) * PAD + lr] = kvv.x;
            Ks[(k + 1) * PAD + lr] = kvv.y;
            Ks[(k + 2) * PAD + lr] = kvv.z;
            Ks[(k + 3) * PAD + lr] = kvv.w;
            float4 vv = *(const float4*)&g_V[(kv0 + lr) * DIM + head * HD + k];
            *(float4*)&Vs[lr * PAD + k] = vv;
        }
        __syncthreads();

        // S = Q K^T (scaled): s[i][j] over 4 q-rows x 4 kv-cols
        float s[4][4] = {};
        #pragma unroll 8
        for (int kk = 0; kk < 64; kk++) {
            float4 a = *(float4*)&Qs[kk * PAD + ty * 4];
            float4 b = *(float4*)&Ks[kk * PAD + tx * 4];
            s[0][0] += a.x * b.x; s[0][1] += a.x * b.y; s[0][2] += a.x * b.z; s[0][3] += a.x * b.w;
            s[1][0] += a.y * b.x; s[1][1] += a.y * b.y; s[1][2] += a.y * b.z; s[1][3] += a.y * b.w;
            s[2][0] += a.z * b.x; s[2][1] += a.z * b.y; s[2][2] += a.z * b.z; s[2][3] += a.z * b.w;
            s[3][0] += a.w * b.x; s[3][1] += a.w * b.y; s[3][2] += a.w * b.z; s[3][3] += a.w * b.w;
        }

        // Online softmax per q-row (reduce across the 16 tx lanes)
        #pragma unroll
        for (int i = 0; i < 4; i++) {
            float mx = fmaxf(fmaxf(s[i][0], s[i][1]), fmaxf(s[i][2], s[i][3]));
            mx = fmaxf(mx, __shfl_xor_sync(0xffffffffu, mx, 8));
            mx = fmaxf(mx, __shfl_xor_sync(0xffffffffu, mx, 4));
            mx = fmaxf(mx, __shfl_xor_sync(0xffffffffu, mx, 2));
            mx = fmaxf(mx, __shfl_xor_sync(0xffffffffu, mx, 1));
            float mn    = fmaxf(m_[i], mx);
            float alpha = __expf(m_[i] - mn);
            m_[i] = mn;
            float rs = 0.f;
            #pragma unroll
            for (int j = 0; j < 4; j++) {
                s[i][j] = __expf(s[i][j] - mn);
                rs += s[i][j];
            }
            rs += __shfl_xor_sync(0xffffffffu, rs, 8);
            rs += __shfl_xor_sync(0xffffffffu, rs, 4);
            rs += __shfl_xor_sync(0xffffffffu, rs, 2);
            rs += __shfl_xor_sync(0xffffffffu, rs, 1);
            l_[i] = l_[i] * alpha + rs;
            #pragma unroll
            for (int j = 0; j < 4; j++) acc[i][j] *= alpha;
            *(float4*)&Ps[(ty * 4 + i) * PAD + tx * 4] =
                make_float4(s[i][0], s[i][1], s[i][2], s[i][3]);
        }
        __syncthreads();

        // acc += P @ V  (P scalar reads broadcast across tx; V float4)
        #pragma unroll 4
        for (int kk = 0; kk < 64; kk++) {
            float4 v = *(float4*)&Vs[kk * PAD + tx * 4];
            #pragma unroll
            for (int i = 0; i < 4; i++) {
                float p = Ps[(ty * 4 + i) * PAD + kk];
                acc[i][0] += p * v.x;
                acc[i][1] += p * v.y;
                acc[i][2] += p * v.z;
                acc[i][3] += p * v.w;
            }
        }
    }

    // Normalize and write ctx in (N, H*HD) layout
    #pragma unroll
    for (int i = 0; i < 4; i++) {
        float inv = 1.f / l_[i];
        float4 o;
        o.x = acc[i][0] * inv;
        o.y = acc[i][1] * inv;
        o.z = acc[i][2] * inv;
        o.w = acc[i][3] * inv;
        *(float4*)&g_ctx[(q0 + ty * 4 + i) * DIM + head * HD + tx * 4] = o;
    }
}

// ---------------------------------------------------------------------------
extern "C" void kernel_launch(void* const* d_in, const int* in_sizes, int n_in,
                              void* d_out, int out_size)
{
    const float* x  = (const float*)d_in[0];
    const float* Wq = (const float*)d_in[1];
    const float* bq = (const float*)d_in[2];
    const float* Wk = (const float*)d_in[3];
    const float* bk = (const float*)d_in[4];
    const float* Wv = (const float*)d_in[5];
    const float* bv = (const float*)d_in[6];
    const float* Wo = (const float*)d_in[7];
    const float* bo = (const float*)d_in[8];
    float* out = (float*)d_out;

    float *Q, *K, *V, *ctx;
    cudaGetSymbolAddress((void**)&Q,   g_Q);
    cudaGetSymbolAddress((void**)&K,   g_K);
    cudaGetSymbolAddress((void**)&V,   g_V);
    cudaGetSymbolAddress((void**)&ctx, g_ctx);

    dim3 blk(16, 16);
    dim3 grd_gemm(DIM / 64, SEQ / 64);   // (8, 64)

    gemm_bias_kernel<<<grd_gemm, blk>>>(x, Wq, bq, Q);
    gemm_bias_kernel<<<grd_gemm, blk>>>(x, Wk, bk, K);
    gemm_bias_kernel<<<grd_gemm, blk>>>(x, Wv, bv, V);

    const int attn_smem = 4 * 64 * PAD * (int)sizeof(float);   // 69632 B
    cudaFuncSetAttribute(attn_kernel,
                         cudaFuncAttributeMaxDynamicSharedMemorySize, attn_smem);
    attn_kernel<<<dim3(SEQ / 64, NH), blk, attn_smem>>>();

    gemm_bias_kernel<<<grd_gemm, blk>>>(ctx, Wo, bo, out);
}

// round 3
// speedup vs baseline: 2.3708x; 2.3708x over previous
#include <cuda_runtime.h>
#include <cuda_bf16.h>
#include <math.h>
#include <cstdint>

// Problem constants
#define SEQ   4096
#define DIM   512
#define NH    8
#define HD    64
#define PAD   68        // smem row stride (floats) for SIMT GEMM

// ---------------------------------------------------------------------------
// Scratch (allocation-free rule: __device__ globals)
// ---------------------------------------------------------------------------
__device__ float g_Q[SEQ * DIM];
__device__ float g_K[SEQ * DIM];
__device__ float g_V[SEQ * DIM];
__device__ float g_ctx[SEQ * DIM];

__device__ __nv_bfloat16 g_Qh[SEQ * DIM];
__device__ __nv_bfloat16 g_Ql[SEQ * DIM];
__device__ __nv_bfloat16 g_Kh[SEQ * DIM];
__device__ __nv_bfloat16 g_Kl[SEQ * DIM];
// V transposed per head: [head][hd=64][seq=4096]
__device__ __nv_bfloat16 g_Vth[NH * HD * SEQ];
__device__ __nv_bfloat16 g_Vtl[NH * HD * SEQ];

// ---------------------------------------------------------------------------
// warp-mma helpers (baseline PTX: sm_80 mma.sync + sm_75 ldmatrix)
// ---------------------------------------------------------------------------
__device__ __forceinline__ uint32_t smem_to_u32(const void* p) {
    uint32_t a;
    asm("{ .reg .u64 t; cvta.to.shared.u64 t, %1; cvt.u32.u64 %0, t; }"
        : "=r"(a) : "l"(p));
    return a;
}

#define SWZ(b) ((b) ^ (((b) >> 3) & 0x70))

__device__ __forceinline__ void ldsm_x4(uint32_t addr, uint32_t& r0, uint32_t& r1,
                                        uint32_t& r2, uint32_t& r3) {
    asm volatile("ldmatrix.sync.aligned.m8n8.x4.shared.b16 {%0,%1,%2,%3}, [%4];"
                 : "=r"(r0), "=r"(r1), "=r"(r2), "=r"(r3) : "r"(addr));
}

__device__ __forceinline__ void mma_bf16(float& d0, float& d1, float& d2, float& d3,
                                         uint32_t a0, uint32_t a1, uint32_t a2, uint32_t a3,
                                         uint32_t b0, uint32_t b1) {
    asm volatile("mma.sync.aligned.m16n8k16.row.col.f32.bf16.bf16.f32 "
                 "{%0,%1,%2,%3}, {%4,%5,%6,%7}, {%8,%9}, {%0,%1,%2,%3};"
                 : "+f"(d0), "+f"(d1), "+f"(d2), "+f"(d3)
                 : "r"(a0), "r"(a1), "r"(a2), "r"(a3), "r"(b0), "r"(b1));
}

// ---------------------------------------------------------------------------
// SIMT GEMM (unchanged): C[4096][512] = X @ W^T + bias
// ---------------------------------------------------------------------------
__global__ __launch_bounds__(256) void gemm_bias_kernel(
    const float* __restrict__ X, const float* __restrict__ W,
    const float* __restrict__ bias, float* __restrict__ C)
{
    __shared__ float Xs[64 * PAD];
    __shared__ float Ws[64 * PAD];
    const int tx = threadIdx.x, ty = threadIdx.y;
    const int t  = ty * 16 + tx;
    const int m0 = blockIdx.y * 64, n0 = blockIdx.x * 64;
    const int lr = t & 63, lk = (t >> 6) * 16;
    float acc[4][4] = {};
    for (int k0 = 0; k0 < DIM; k0 += 64) {
        #pragma unroll
        for (int i = 0; i < 4; i++) {
            int k = lk + i * 4;
            float4 xv = *(const float4*)&X[(m0 + lr) * DIM + k0 + k];
            Xs[(k+0)*PAD+lr]=xv.x; Xs[(k+1)*PAD+lr]=xv.y; Xs[(k+2)*PAD+lr]=xv.z; Xs[(k+3)*PAD+lr]=xv.w;
            float4 wv = *(const float4*)&W[(n0 + lr) * DIM + k0 + k];
            Ws[(k+0)*PAD+lr]=wv.x; Ws[(k+1)*PAD+lr]=wv.y; Ws[(k+2)*PAD+lr]=wv.z; Ws[(k+3)*PAD+lr]=wv.w;
        }
        __syncthreads();
        #pragma unroll 8
        for (int kk = 0; kk < 64; kk++) {
            float4 a = *(float4*)&Xs[kk*PAD + ty*4];
            float4 b = *(float4*)&Ws[kk*PAD + tx*4];
            acc[0][0]+=a.x*b.x; acc[0][1]+=a.x*b.y; acc[0][2]+=a.x*b.z; acc[0][3]+=a.x*b.w;
            acc[1][0]+=a.y*b.x; acc[1][1]+=a.y*b.y; acc[1][2]+=a.y*b.z; acc[1][3]+=a.y*b.w;
            acc[2][0]+=a.z*b.x; acc[2][1]+=a.z*b.y; acc[2][2]+=a.z*b.z; acc[2][3]+=a.z*b.w;
            acc[3][0]+=a.w*b.x; acc[3][1]+=a.w*b.y; acc[3][2]+=a.w*b.z; acc[3][3]+=a.w*b.w;
        }
        __syncthreads();
    }
    float4 bv = *(const float4*)&bias[n0 + tx*4];
    #pragma unroll
    for (int i = 0; i < 4; i++) {
        float4 o = { acc[i][0]+bv.x, acc[i][1]+bv.y, acc[i][2]+bv.z, acc[i][3]+bv.w };
        *(float4*)&C[(m0 + ty*4 + i) * DIM + n0 + tx*4] = o;
    }
}

// ---------------------------------------------------------------------------
// fp32 -> bf16 hi/lo conversion
// ---------------------------------------------------------------------------
__global__ void convert_hl_kernel(const float* __restrict__ src,
                                  __nv_bfloat16* __restrict__ dh,
                                  __nv_bfloat16* __restrict__ dl,
                                  float scale, int n)
{
    int i = blockIdx.x * blockDim.x + threadIdx.x;
    int stride = gridDim.x * blockDim.x;
    for (; i < n; i += stride) {
        float v = src[i] * scale;
        __nv_bfloat16 h = __float2bfloat16(v);
        dh[i] = h;
        dl[i] = __float2bfloat16(v - __bfloat162float(h));
    }
}

// V -> transposed per-head [head][hd][seq] bf16 hi/lo
__global__ __launch_bounds__(256) void convert_vt_kernel()
{
    __shared__ float tile[64][65];
    int h = blockIdx.y, s0 = blockIdx.x * 64;
    int t = threadIdx.x;
    #pragma unroll
    for (int i = 0; i < 16; i++) {
        int idx = i * 256 + t;
        int r = idx >> 6, c = idx & 63;
        tile[r][c] = g_V[(s0 + r) * DIM + h * HD + c];
    }
    __syncthreads();
    #pragma unroll
    for (int i = 0; i < 16; i++) {
        int idx = i * 256 + t;
        int c = idx >> 6, r = idx & 63;
        float v = tile[r][c];
        __nv_bfloat16 hb = __float2bfloat16(v);
        __nv_bfloat16 lb = __float2bfloat16(v - __bfloat162float(hb));
        g_Vth[(h * HD + c) * SEQ + s0 + r] = hb;
        g_Vtl[(h * HD + c) * SEQ + s0 + r] = lb;
    }
}

// ---------------------------------------------------------------------------
// Flash attention via mma.sync bf16 hi/lo (3-pass).
// CTA: 128 q-rows x head, 256 threads = 8 warps, each warp owns 16 q-rows.
// kv tile = 64. Smem: Kh,Kl [64 kv][64 d], Vh,Vl [64 hd][64 kv], SW128 swizzle.
// ---------------------------------------------------------------------------
#define SMB_KH 0
#define SMB_KL 8192
#define SMB_VH 16384
#define SMB_VL 24576
#define SMB_TOTAL 32768

// Stage a 64x64 bf16 tile (row-major source, stride in elements) into swizzled smem
__device__ __forceinline__ void stage_tile64(char* dst, const __nv_bfloat16* src,
                                             size_t stride)
{
    const int t = threadIdx.x;
    #pragma unroll
    for (int i = 0; i < 2; i++) {
        int c = i * 256 + t;                 // 512 16B chunks
        int row = c >> 3, colb = (c & 7) * 16;
        float4 v = *(const float4*)(const void*)(src + (size_t)row * stride + (c & 7) * 8);
        *(float4*)(dst + SWZ(row * 128 + colb)) = v;
    }
}

__global__ __launch_bounds__(256) void attn_mma_kernel()
{
    extern __shared__ char smem[];
    const uint32_t sb = smem_to_u32(smem);
    const int tid  = threadIdx.x;
    const int w    = tid >> 5;
    const int l    = tid & 31;
    const int head = blockIdx.y;
    const int q0   = blockIdx.x * 128;

    // lane patterns (ldmatrix address groups)
    const int qrow = (l & 7) + ((l >> 3) & 1) * 8;   // A-frag: row within m16
    const int qkb  = ((l >> 4) & 1) * 16;            // A-frag: k-byte half
    const int bn   = (l & 7) + ((l >> 4) & 1) * 8;   // B-frag: n within n16 pair
    const int bkb  = ((l >> 3) & 1) * 16;            // B-frag: k-byte half

    // ---- stage Q (128 rows x 64) into smem (reusing K area), extract frags ----
    uint32_t qh[4][4], ql[4][4];
    {
        const int t = tid;
        #pragma unroll
        for (int i = 0; i < 4; i++) {                 // 1024 chunks for 128 rows
            int c = i * 256 + t;
            int row = c >> 3, colb = (c & 7) * 16;
            float4 v = *(const float4*)(const void*)
                (g_Qh + (size_t)(q0 + row) * DIM + head * HD + (c & 7) * 8);
            *(float4*)(smem + SWZ(row * 128 + colb)) = v;
        }
        __syncthreads();
        #pragma unroll
        for (int kt = 0; kt < 4; kt++) {
            uint32_t a = sb + SWZ((w * 16 + qrow) * 128 + kt * 32 + qkb);
            ldsm_x4(a, qh[kt][0], qh[kt][1], qh[kt][2], qh[kt][3]);
        }
        __syncthreads();
        #pragma unroll
        for (int i = 0; i < 4; i++) {
            int c = i * 256 + t;
            int row = c >> 3, colb = (c & 7) * 16;
            float4 v = *(const float4*)(const void*)
                (g_Ql + (size_t)(q0 + row) * DIM + head * HD + (c & 7) * 8);
            *(float4*)(smem + SWZ(row * 128 + colb)) = v;
        }
        __syncthreads();
        #pragma unroll
        for (int kt = 0; kt < 4; kt++) {
            uint32_t a = sb + SWZ((w * 16 + qrow) * 128 + kt * 32 + qkb);
            ldsm_x4(a, ql[kt][0], ql[kt][1], ql[kt][2], ql[kt][3]);
        }
    }

    // running stats & output accumulators (8 n-tiles of hd)
    float m0 = -1e30f, m1 = -1e30f;   // rows r and r+8 (r = l>>2)
    float l0 = 0.f, l1 = 0.f;         // per-lane partial row sums
    float O[8][4];
    #pragma unroll
    for (int nt = 0; nt < 8; nt++)
        #pragma unroll
        for (int j = 0; j < 4; j++) O[nt][j] = 0.f;

    for (int kv0 = 0; kv0 < SEQ; kv0 += 64) {
        __syncthreads();   // previous iteration's ldmatrix reads finished
        stage_tile64(smem + SMB_KH, g_Kh + (size_t)kv0 * DIM + head * HD, DIM);
        stage_tile64(smem + SMB_KL, g_Kl + (size_t)kv0 * DIM + head * HD, DIM);
        stage_tile64(smem + SMB_VH, g_Vth + (size_t)head * HD * SEQ + kv0, SEQ);
        stage_tile64(smem + SMB_VL, g_Vtl + (size_t)head * HD * SEQ + kv0, SEQ);
        __syncthreads();

        // ---- S = Q K^T (hi/lo 3-pass), 8 n-tiles of kv ----
        float s[8][4];
        #pragma unroll
        for (int nt = 0; nt < 8; nt++)
            #pragma unroll
            for (int j = 0; j < 4; j++) s[nt][j] = 0.f;

        #pragma unroll
        for (int ntp = 0; ntp < 4; ntp++) {          // n-pair (16 kv rows)
            #pragma unroll
            for (int kt = 0; kt < 4; kt++) {
                uint32_t off = SWZ((ntp * 16 + bn) * 128 + kt * 32 + bkb);
                uint32_t kh0, kh1, kh2, kh3, kl0, kl1, kl2, kl3;
                ldsm_x4(sb + SMB_KH + off, kh0, kh1, kh2, kh3);
                ldsm_x4(sb + SMB_KL + off, kl0, kl1, kl2, kl3);
                float* sa = s[2 * ntp];
                float* sc = s[2 * ntp + 1];
                mma_bf16(sa[0], sa[1], sa[2], sa[3], qh[kt][0], qh[kt][1], qh[kt][2], qh[kt][3], kh0, kh1);
                mma_bf16(sa[0], sa[1], sa[2], sa[3], ql[kt][0], ql[kt][1], ql[kt][2], ql[kt][3], kh0, kh1);
                mma_bf16(sa[0], sa[1], sa[2], sa[3], qh[kt][0], qh[kt][1], qh[kt][2], qh[kt][3], kl0, kl1);
                mma_bf16(sc[0], sc[1], sc[2], sc[3], qh[kt][0], qh[kt][1], qh[kt][2], qh[kt][3], kh2, kh3);
                mma_bf16(sc[0], sc[1], sc[2], sc[3], ql[kt][0], ql[kt][1], ql[kt][2], ql[kt][3], kh2, kh3);
                mma_bf16(sc[0], sc[1], sc[2], sc[3], qh[kt][0], qh[kt][1], qh[kt][2], qh[kt][3], kl2, kl3);
            }
        }

        // ---- online softmax (rows r = l>>2 and r+8) ----
        float mx0 = m0, mx1 = m1;
        #pragma unroll
        for (int nt = 0; nt < 8; nt++) {
            mx0 = fmaxf(mx0, fmaxf(s[nt][0], s[nt][1]));
            mx1 = fmaxf(mx1, fmaxf(s[nt][2], s[nt][3]));
        }
        mx0 = fmaxf(mx0, __shfl_xor_sync(0xffffffffu, mx0, 1));
        mx0 = fmaxf(mx0, __shfl_xor_sync(0xffffffffu, mx0, 2));
        mx1 = fmaxf(mx1, __shfl_xor_sync(0xffffffffu, mx1, 1));
        mx1 = fmaxf(mx1, __shfl_xor_sync(0xffffffffu, mx1, 2));
        const float alpha0 = __expf(m0 - mx0);
        const float alpha1 = __expf(m1 - mx1);
        m0 = mx0; m1 = mx1;

        // P = exp(S - m), fp32 -> bf16 hi/lo packed as A-fragments (k-tile kt
        // <- S n-tiles 2kt, 2kt+1)
        uint32_t ph[4][4], pl[4][4];
        float rs0 = 0.f, rs1 = 0.f;
        #pragma unroll
        for (int nt = 0; nt < 8; nt++) {
            float p0 = __expf(s[nt][0] - mx0);
            float p1 = __expf(s[nt][1] - mx0);
            float p2 = __expf(s[nt][2] - mx1);
            float p3 = __expf(s[nt][3] - mx1);
            rs0 += p0 + p1; rs1 += p2 + p3;
            __nv_bfloat162 h01 = __floats2bfloat162_rn(p0, p1);
            __nv_bfloat162 h23 = __floats2bfloat162_rn(p2, p3);
            __nv_bfloat162 l01 = __floats2bfloat162_rn(p0 - __bfloat162float(h01.x),
                                                       p1 - __bfloat162float(h01.y));
            __nv_bfloat162 l23 = __floats2bfloat162_rn(p2 - __bfloat162float(h23.x),
                                                       p3 - __bfloat162float(h23.y));
            const int kt = nt >> 1, hi = (nt & 1) * 2;
            ph[kt][hi + 0] = *(uint32_t*)&h01;
            ph[kt][hi + 1] = *(uint32_t*)&h23;
            pl[kt][hi + 0] = *(uint32_t*)&l01;
            pl[kt][hi + 1] = *(uint32_t*)&l23;
        }
        l0 = l0 * alpha0 + rs0;
        l1 = l1 * alpha1 + rs1;

        // rescale O then accumulate P @ V (hi/lo 3-pass)
        #pragma unroll
        for (int nt = 0; nt < 8; nt++) {
            O[nt][0] *= alpha0; O[nt][1] *= alpha0;
            O[nt][2] *= alpha1; O[nt][3] *= alpha1;
        }
        #pragma unroll
        for (int ntp = 0; ntp < 4; ntp++) {          // n-pair (16 hd cols)
            #pragma unroll
            for (int kt = 0; kt < 4; kt++) {
                uint32_t off = SWZ((ntp * 16 + bn) * 128 + kt * 32 + bkb);
                uint32_t vh0, vh1, vh2, vh3, vl0, vl1, vl2, vl3;
                ldsm_x4(sb + SMB_VH + off, vh0, vh1, vh2, vh3);
                ldsm_x4(sb + SMB_VL + off, vl0, vl1, vl2, vl3);
                float* oa = O[2 * ntp];
                float* oc = O[2 * ntp + 1];
                mma_bf16(oa[0], oa[1], oa[2], oa[3], ph[kt][0], ph[kt][1], ph[kt][2], ph[kt][3], vh0, vh1);
                mma_bf16(oa[0], oa[1], oa[2], oa[3], pl[kt][0], pl[kt][1], pl[kt][2], pl[kt][3], vh0, vh1);
                mma_bf16(oa[0], oa[1], oa[2], oa[3], ph[kt][0], ph[kt][1], ph[kt][2], ph[kt][3], vl0, vl1);
                mma_bf16(oc[0], oc[1], oc[2], oc[3], ph[kt][0], ph[kt][1], ph[kt][2], ph[kt][3], vh2, vh3);
                mma_bf16(oc[0], oc[1], oc[2], oc[3], pl[kt][0], pl[kt][1], pl[kt][2], pl[kt][3], vh2, vh3);
                mma_bf16(oc[0], oc[1], oc[2], oc[3], ph[kt][0], ph[kt][1], ph[kt][2], ph[kt][3], vl2, vl3);
            }
        }
    }

    // full row sums (quad reduce) and output
    l0 += __shfl_xor_sync(0xffffffffu, l0, 1);
    l0 += __shfl_xor_sync(0xffffffffu, l0, 2);
    l1 += __shfl_xor_sync(0xffffffffu, l1, 1);
    l1 += __shfl_xor_sync(0xffffffffu, l1, 2);
    const float inv0 = 1.f / l0, inv1 = 1.f / l1;
    const int r = l >> 2, cc = (l & 3) * 2;
    float* base0 = &g_ctx[(size_t)(q0 + w * 16 + r)     * DIM + head * HD];
    float* base1 = &g_ctx[(size_t)(q0 + w * 16 + r + 8) * DIM + head * HD];
    #pragma unroll
    for (int nt = 0; nt < 8; nt++) {
        float2 o0 = { O[nt][0] * inv0, O[nt][1] * inv0 };
        float2 o1 = { O[nt][2] * inv1, O[nt][3] * inv1 };
        *(float2*)(base0 + nt * 8 + cc) = o0;
        *(float2*)(base1 + nt * 8 + cc) = o1;
    }
}

// ---------------------------------------------------------------------------
extern "C" void kernel_launch(void* const* d_in, const int* in_sizes, int n_in,
                              void* d_out, int out_size)
{
    const float* x  = (const float*)d_in[0];
    const float* Wq = (const float*)d_in[1];
    const float* bq = (const float*)d_in[2];
    const float* Wk = (const float*)d_in[3];
    const float* bk = (const float*)d_in[4];
    const float* Wv = (const float*)d_in[5];
    const float* bv = (const float*)d_in[6];
    const float* Wo = (const float*)d_in[7];
    const float* bo = (const float*)d_in[8];
    float* out = (float*)d_out;

    float *Q, *K, *V, *ctx;
    cudaGetSymbolAddress((void**)&Q,   g_Q);
    cudaGetSymbolAddress((void**)&K,   g_K);
    cudaGetSymbolAddress((void**)&V,   g_V);
    cudaGetSymbolAddress((void**)&ctx, g_ctx);
    __nv_bfloat16 *Qh, *Ql, *Kh, *Kl;
    cudaGetSymbolAddress((void**)&Qh, g_Qh);
    cudaGetSymbolAddress((void**)&Ql, g_Ql);
    cudaGetSymbolAddress((void**)&Kh, g_Kh);
    cudaGetSymbolAddress((void**)&Kl, g_Kl);

    dim3 blk(16, 16);
    dim3 grd_gemm(DIM / 64, SEQ / 64);

    gemm_bias_kernel<<<grd_gemm, blk>>>(x, Wq, bq, Q);
    gemm_bias_kernel<<<grd_gemm, blk>>>(x, Wk, bk, K);
    gemm_bias_kernel<<<grd_gemm, blk>>>(x, Wv, bv, V);

    const int n = SEQ * DIM;
    convert_hl_kernel<<<1024, 256>>>(Q, Qh, Ql, 0.125f, n);   // fold 1/sqrt(64)
    convert_hl_kernel<<<1024, 256>>>(K, Kh, Kl, 1.0f,   n);
    convert_vt_kernel<<<dim3(SEQ / 64, NH), 256>>>();

    attn_mma_kernel<<<dim3(SEQ / 128, NH), 256, SMB_TOTAL>>>();

    gemm_bias_kernel<<<grd_gemm, blk>>>(ctx, Wo, bo, out);
}

// round 4
// speedup vs baseline: 3.8122x; 1.6080x over previous
#include <cuda_runtime.h>
#include <cuda_bf16.h>
#include <math.h>
#include <cstdint>

// Problem constants
#define SEQ   4096
#define DIM   512
#define NH    8
#define HD    64

// ---------------------------------------------------------------------------
// Scratch (allocation-free rule: __device__ globals)
// ---------------------------------------------------------------------------
__device__ float g_V[SEQ * DIM];

__device__ __nv_bfloat16 g_xh[SEQ * DIM];
__device__ __nv_bfloat16 g_xl[SEQ * DIM];
__device__ __nv_bfloat16 g_Wqh[DIM * DIM], g_Wql[DIM * DIM];
__device__ __nv_bfloat16 g_Wkh[DIM * DIM], g_Wkl[DIM * DIM];
__device__ __nv_bfloat16 g_Wvh[DIM * DIM], g_Wvl[DIM * DIM];
__device__ __nv_bfloat16 g_Woh[DIM * DIM], g_Wol[DIM * DIM];

__device__ __nv_bfloat16 g_Qh[SEQ * DIM];
__device__ __nv_bfloat16 g_Ql[SEQ * DIM];
__device__ __nv_bfloat16 g_Kh[SEQ * DIM];
__device__ __nv_bfloat16 g_Kl[SEQ * DIM];
// V transposed per head: [head][hd=64][seq=4096]
__device__ __nv_bfloat16 g_Vth[NH * HD * SEQ];
__device__ __nv_bfloat16 g_Vtl[NH * HD * SEQ];
// attention output, bf16 hi/lo split (feeds final GEMM)
__device__ __nv_bfloat16 g_ctxh[SEQ * DIM];
__device__ __nv_bfloat16 g_ctxl[SEQ * DIM];

// ---------------------------------------------------------------------------
// warp-mma helpers (baseline PTX: sm_80 mma.sync + sm_75 ldmatrix + cp.async)
// ---------------------------------------------------------------------------
__device__ __forceinline__ uint32_t smem_to_u32(const void* p) {
    uint32_t a;
    asm("{ .reg .u64 t; cvta.to.shared.u64 t, %1; cvt.u32.u64 %0, t; }"
        : "=r"(a) : "l"(p));
    return a;
}

#define SWZ(b) ((b) ^ (((b) >> 3) & 0x70))

__device__ __forceinline__ void ldsm_x4(uint32_t addr, uint32_t& r0, uint32_t& r1,
                                        uint32_t& r2, uint32_t& r3) {
    asm volatile("ldmatrix.sync.aligned.m8n8.x4.shared.b16 {%0,%1,%2,%3}, [%4];"
                 : "=r"(r0), "=r"(r1), "=r"(r2), "=r"(r3) : "r"(addr));
}

__device__ __forceinline__ void mma_bf16(float& d0, float& d1, float& d2, float& d3,
                                         uint32_t a0, uint32_t a1, uint32_t a2, uint32_t a3,
                                         uint32_t b0, uint32_t b1) {
    asm volatile("mma.sync.aligned.m16n8k16.row.col.f32.bf16.bf16.f32 "
                 "{%0,%1,%2,%3}, {%4,%5,%6,%7}, {%8,%9}, {%0,%1,%2,%3};"
                 : "+f"(d0), "+f"(d1), "+f"(d2), "+f"(d3)
                 : "r"(a0), "r"(a1), "r"(a2), "r"(a3), "r"(b0), "r"(b1));
}

__device__ __forceinline__ void cp16(uint32_t dst, const void* src) {
    asm volatile("cp.async.cg.shared.global [%0], [%1], 16;" :: "r"(dst), "l"(src));
}
#define CP_COMMIT() asm volatile("cp.async.commit_group;" ::: "memory")
template <int N>
__device__ __forceinline__ void cp_wait() {
    asm volatile("cp.async.wait_group %0;" :: "n"(N) : "memory");
}

// ---------------------------------------------------------------------------
// fp32 -> bf16 hi/lo conversion
// ---------------------------------------------------------------------------
__global__ void convert_hl_kernel(const float* __restrict__ src,
                                  __nv_bfloat16* __restrict__ dh,
                                  __nv_bfloat16* __restrict__ dl,
                                  float scale, int n)
{
    int i = blockIdx.x * blockDim.x + threadIdx.x;
    int stride = gridDim.x * blockDim.x;
    for (; i < n; i += stride) {
        float v = src[i] * scale;
        __nv_bfloat16 h = __float2bfloat16(v);
        dh[i] = h;
        dl[i] = __float2bfloat16(v - __bfloat162float(h));
    }
}

// V -> transposed per-head [head][hd][seq] bf16 hi/lo
__global__ __launch_bounds__(256) void convert_vt_kernel()
{
    __shared__ float tile[64][65];
    int h = blockIdx.y, s0 = blockIdx.x * 64;
    int t = threadIdx.x;
    #pragma unroll
    for (int i = 0; i < 16; i++) {
        int idx = i * 256 + t;
        int r = idx >> 6, c = idx & 63;
        tile[r][c] = g_V[(s0 + r) * DIM + h * HD + c];
    }
    __syncthreads();
    #pragma unroll
    for (int i = 0; i < 16; i++) {
        int idx = i * 256 + t;
        int c = idx >> 6, r = idx & 63;
        float v = tile[r][c];
        __nv_bfloat16 hb = __float2bfloat16(v);
        __nv_bfloat16 lb = __float2bfloat16(v - __bfloat162float(hb));
        g_Vth[(h * HD + c) * SEQ + s0 + r] = hb;
        g_Vtl[(h * HD + c) * SEQ + s0 + r] = lb;
    }
}

// ---------------------------------------------------------------------------
// Tensor-core GEMM: C[M=4096][N=512] = A @ B^T + bias, bf16 hi/lo 3-pass.
// CTA tile 128M x 64N, warp grid 4(M) x 2(N), warp tile 32x32.
// K-chunks of 64, cp.async double-buffered, SW128-swizzled smem.
// mode 0: write fp32 Cf (scale applied).  mode 1: write bf16 hi/lo Ch/Cl.
// ---------------------------------------------------------------------------
#define GOFF_AH 0
#define GOFF_AL 16384
#define GOFF_BH 32768
#define GOFF_BL 40960
#define GBUF    49152
#define GSMEM   (2 * GBUF)   // 98304

__device__ __forceinline__ void gemm_stage_chunk(
    uint32_t sbuf,
    const __nv_bfloat16* __restrict__ Ah, const __nv_bfloat16* __restrict__ Al,
    const __nv_bfloat16* __restrict__ Bh, const __nv_bfloat16* __restrict__ Bl,
    int m0, int n0, int k0, int tid)
{
    #pragma unroll
    for (int i = 0; i < 4; i++) {                  // A: 128 rows x 64 cols
        int c = i * 256 + tid;
        int row = c >> 3, col = c & 7;
        uint32_t off = SWZ((uint32_t)(row * 128 + col * 16));
        size_t gidx = (size_t)(m0 + row) * DIM + k0 + col * 8;
        cp16(sbuf + GOFF_AH + off, Ah + gidx);
        cp16(sbuf + GOFF_AL + off, Al + gidx);
    }
    #pragma unroll
    for (int i = 0; i < 2; i++) {                  // B: 64 rows x 64 cols
        int c = i * 256 + tid;
        int row = c >> 3, col = c & 7;
        uint32_t off = SWZ((uint32_t)(row * 128 + col * 16));
        size_t gidx = (size_t)(n0 + row) * DIM + k0 + col * 8;
        cp16(sbuf + GOFF_BH + off, Bh + gidx);
        cp16(sbuf + GOFF_BL + off, Bl + gidx);
    }
}

__global__ __launch_bounds__(256) void gemm_tc_kernel(
    const __nv_bfloat16* __restrict__ Ah, const __nv_bfloat16* __restrict__ Al,
    const __nv_bfloat16* __restrict__ Bh, const __nv_bfloat16* __restrict__ Bl,
    const float* __restrict__ bias,
    float* __restrict__ Cf,
    __nv_bfloat16* __restrict__ Ch, __nv_bfloat16* __restrict__ Cl,
    float scale, int mode)
{
    extern __shared__ char smem[];
    const uint32_t sb = smem_to_u32(smem);
    const int tid = threadIdx.x;
    const int w   = tid >> 5;
    const int l   = tid & 31;
    const int wm  = w & 3;           // 0..3 -> M
    const int wn  = w >> 2;          // 0..1 -> N
    const int m0  = blockIdx.y * 128;
    const int n0  = blockIdx.x * 64;

    const int qrow = (l & 7) + ((l >> 3) & 1) * 8;   // A-frag row pattern
    const int qkb  = ((l >> 4) & 1) * 16;            // A-frag k-byte half
    const int bn   = (l & 7) + ((l >> 4) & 1) * 8;   // B-frag n pattern
    const int bkb  = ((l >> 3) & 1) * 16;            // B-frag k-byte half

    float acc[2][4][4];
    #pragma unroll
    for (int mf = 0; mf < 2; mf++)
        #pragma unroll
        for (int j = 0; j < 4; j++)
            #pragma unroll
            for (int q = 0; q < 4; q++) acc[mf][j][q] = 0.f;

    gemm_stage_chunk(sb, Ah, Al, Bh, Bl, m0, n0, 0, tid);
    CP_COMMIT();

    for (int ch = 0; ch < 8; ch++) {
        if (ch < 7) {
            gemm_stage_chunk(sb + ((ch + 1) & 1) * GBUF, Ah, Al, Bh, Bl,
                             m0, n0, (ch + 1) * 64, tid);
            CP_COMMIT();
            cp_wait<1>();
        } else {
            cp_wait<0>();
        }
        __syncthreads();

        const uint32_t b = sb + (ch & 1) * GBUF;
        #pragma unroll
        for (int kt = 0; kt < 4; kt++) {
            uint32_t ah[2][4], al[2][4];
            #pragma unroll
            for (int mf = 0; mf < 2; mf++) {
                uint32_t aoff = SWZ((uint32_t)((wm * 32 + mf * 16 + qrow) * 128 + kt * 32 + qkb));
                ldsm_x4(b + GOFF_AH + aoff, ah[mf][0], ah[mf][1], ah[mf][2], ah[mf][3]);
                ldsm_x4(b + GOFF_AL + aoff, al[mf][0], al[mf][1], al[mf][2], al[mf][3]);
            }
            #pragma unroll
            for (int np = 0; np < 2; np++) {
                uint32_t boff = SWZ((uint32_t)((wn * 32 + np * 16 + bn) * 128 + kt * 32 + bkb));
                uint32_t bh0, bh1, bh2, bh3, bl0, bl1, bl2, bl3;
                ldsm_x4(b + GOFF_BH + boff, bh0, bh1, bh2, bh3);
                ldsm_x4(b + GOFF_BL + boff, bl0, bl1, bl2, bl3);
                #pragma unroll
                for (int mf = 0; mf < 2; mf++) {
                    float* a0 = acc[mf][2 * np];
                    float* a1 = acc[mf][2 * np + 1];
                    mma_bf16(a0[0], a0[1], a0[2], a0[3], ah[mf][0], ah[mf][1], ah[mf][2], ah[mf][3], bh0, bh1);
                    mma_bf16(a0[0], a0[1], a0[2], a0[3], al[mf][0], al[mf][1], al[mf][2], al[mf][3], bh0, bh1);
                    mma_bf16(a0[0], a0[1], a0[2], a0[3], ah[mf][0], ah[mf][1], ah[mf][2], ah[mf][3], bl0, bl1);
                    mma_bf16(a1[0], a1[1], a1[2], a1[3], ah[mf][0], ah[mf][1], ah[mf][2], ah[mf][3], bh2, bh3);
                    mma_bf16(a1[0], a1[1], a1[2], a1[3], al[mf][0], al[mf][1], al[mf][2], al[mf][3], bh2, bh3);
                    mma_bf16(a1[0], a1[1], a1[2], a1[3], ah[mf][0], ah[mf][1], ah[mf][2], ah[mf][3], bl2, bl3);
                }
            }
        }
        __syncthreads();
    }

    // Epilogue: accum layout d0,d1 -> row r, cols cc,cc+1; d2,d3 -> row r+8
    const int r = l >> 2, cc = (l & 3) * 2;
    #pragma unroll
    for (int mf = 0; mf < 2; mf++) {
        const int mrow = m0 + wm * 32 + mf * 16 + r;
        #pragma unroll
        for (int j = 0; j < 4; j++) {
            const int col = n0 + wn * 32 + (j >> 1) * 16 + (j & 1) * 8 + cc;
            const float b0 = bias[col], b1 = bias[col + 1];
            float v00 = (acc[mf][j][0] + b0) * scale;
            float v01 = (acc[mf][j][1] + b1) * scale;
            float v10 = (acc[mf][j][2] + b0) * scale;
            float v11 = (acc[mf][j][3] + b1) * scale;
            if (mode == 0) {
                *(float2*)&Cf[(size_t)mrow * DIM + col]       = make_float2(v00, v01);
                *(float2*)&Cf[(size_t)(mrow + 8) * DIM + col] = make_float2(v10, v11);
            } else {
                __nv_bfloat162 h0 = __floats2bfloat162_rn(v00, v01);
                __nv_bfloat162 l0 = __floats2bfloat162_rn(v00 - __bfloat162float(h0.x),
                                                          v01 - __bfloat162float(h0.y));
                __nv_bfloat162 h1 = __floats2bfloat162_rn(v10, v11);
                __nv_bfloat162 l1 = __floats2bfloat162_rn(v10 - __bfloat162float(h1.x),
                                                          v11 - __bfloat162float(h1.y));
                *(__nv_bfloat162*)&Ch[(size_t)mrow * DIM + col]       = h0;
                *(__nv_bfloat162*)&Cl[(size_t)mrow * DIM + col]       = l0;
                *(__nv_bfloat162*)&Ch[(size_t)(mrow + 8) * DIM + col] = h1;
                *(__nv_bfloat162*)&Cl[(size_t)(mrow + 8) * DIM + col] = l1;
            }
        }
    }
}

// ---------------------------------------------------------------------------
// Flash attention via mma.sync bf16 hi/lo (3-pass). Unchanged core from R3;
// epilogue now emits bf16 hi/lo ctx directly.
// ---------------------------------------------------------------------------
#define SMB_KH 0
#define SMB_KL 8192
#define SMB_VH 16384
#define SMB_VL 24576
#define SMB_TOTAL 32768

__device__ __forceinline__ void stage_tile64(char* dst, const __nv_bfloat16* src,
                                             size_t stride)
{
    const int t = threadIdx.x;
    #pragma unroll
    for (int i = 0; i < 2; i++) {
        int c = i * 256 + t;
        int row = c >> 3, colb = (c & 7) * 16;
        float4 v = *(const float4*)(const void*)(src + (size_t)row * stride + (c & 7) * 8);
        *(float4*)(dst + SWZ(row * 128 + colb)) = v;
    }
}

__global__ __launch_bounds__(256) void attn_mma_kernel()
{
    extern __shared__ char smem[];
    const uint32_t sb = smem_to_u32(smem);
    const int tid  = threadIdx.x;
    const int w    = tid >> 5;
    const int l    = tid & 31;
    const int head = blockIdx.y;
    const int q0   = blockIdx.x * 128;

    const int qrow = (l & 7) + ((l >> 3) & 1) * 8;
    const int qkb  = ((l >> 4) & 1) * 16;
    const int bn   = (l & 7) + ((l >> 4) & 1) * 8;
    const int bkb  = ((l >> 3) & 1) * 16;

    // stage Q (128x64) into smem, extract persistent fragments
    uint32_t qh[4][4], ql[4][4];
    {
        const int t = tid;
        #pragma unroll
        for (int i = 0; i < 4; i++) {
            int c = i * 256 + t;
            int row = c >> 3, colb = (c & 7) * 16;
            float4 v = *(const float4*)(const void*)
                (g_Qh + (size_t)(q0 + row) * DIM + head * HD + (c & 7) * 8);
            *(float4*)(smem + SWZ(row * 128 + colb)) = v;
        }
        __syncthreads();
        #pragma unroll
        for (int kt = 0; kt < 4; kt++) {
            uint32_t a = sb + SWZ((w * 16 + qrow) * 128 + kt * 32 + qkb);
            ldsm_x4(a, qh[kt][0], qh[kt][1], qh[kt][2], qh[kt][3]);
        }
        __syncthreads();
        #pragma unroll
        for (int i = 0; i < 4; i++) {
            int c = i * 256 + t;
            int row = c >> 3, colb = (c & 7) * 16;
            float4 v = *(const float4*)(const void*)
                (g_Ql + (size_t)(q0 + row) * DIM + head * HD + (c & 7) * 8);
            *(float4*)(smem + SWZ(row * 128 + colb)) = v;
        }
        __syncthreads();
        #pragma unroll
        for (int kt = 0; kt < 4; kt++) {
            uint32_t a = sb + SWZ((w * 16 + qrow) * 128 + kt * 32 + qkb);
            ldsm_x4(a, ql[kt][0], ql[kt][1], ql[kt][2], ql[kt][3]);
        }
    }

    float m0 = -1e30f, m1 = -1e30f;
    float l0 = 0.f, l1 = 0.f;
    float O[8][4];
    #pragma unroll
    for (int nt = 0; nt < 8; nt++)
        #pragma unroll
        for (int j = 0; j < 4; j++) O[nt][j] = 0.f;

    for (int kv0 = 0; kv0 < SEQ; kv0 += 64) {
        __syncthreads();
        stage_tile64(smem + SMB_KH, g_Kh + (size_t)kv0 * DIM + head * HD, DIM);
        stage_tile64(smem + SMB_KL, g_Kl + (size_t)kv0 * DIM + head * HD, DIM);
        stage_tile64(smem + SMB_VH, g_Vth + (size_t)head * HD * SEQ + kv0, SEQ);
        stage_tile64(smem + SMB_VL, g_Vtl + (size_t)head * HD * SEQ + kv0, SEQ);
        __syncthreads();

        float s[8][4];
        #pragma unroll
        for (int nt = 0; nt < 8; nt++)
            #pragma unroll
            for (int j = 0; j < 4; j++) s[nt][j] = 0.f;

        #pragma unroll
        for (int ntp = 0; ntp < 4; ntp++) {
            #pragma unroll
            for (int kt = 0; kt < 4; kt++) {
                uint32_t off = SWZ((ntp * 16 + bn) * 128 + kt * 32 + bkb);
                uint32_t kh0, kh1, kh2, kh3, kl0, kl1, kl2, kl3;
                ldsm_x4(sb + SMB_KH + off, kh0, kh1, kh2, kh3);
                ldsm_x4(sb + SMB_KL + off, kl0, kl1, kl2, kl3);
                float* sa = s[2 * ntp];
                float* sc = s[2 * ntp + 1];
                mma_bf16(sa[0], sa[1], sa[2], sa[3], qh[kt][0], qh[kt][1], qh[kt][2], qh[kt][3], kh0, kh1);
                mma_bf16(sa[0], sa[1], sa[2], sa[3], ql[kt][0], ql[kt][1], ql[kt][2], ql[kt][3], kh0, kh1);
                mma_bf16(sa[0], sa[1], sa[2], sa[3], qh[kt][0], qh[kt][1], qh[kt][2], qh[kt][3], kl0, kl1);
                mma_bf16(sc[0], sc[1], sc[2], sc[3], qh[kt][0], qh[kt][1], qh[kt][2], qh[kt][3], kh2, kh3);
                mma_bf16(sc[0], sc[1], sc[2], sc[3], ql[kt][0], ql[kt][1], ql[kt][2], ql[kt][3], kh2, kh3);
                mma_bf16(sc[0], sc[1], sc[2], sc[3], qh[kt][0], qh[kt][1], qh[kt][2], qh[kt][3], kl2, kl3);
            }
        }

        float mx0 = m0, mx1 = m1;
        #pragma unroll
        for (int nt = 0; nt < 8; nt++) {
            mx0 = fmaxf(mx0, fmaxf(s[nt][0], s[nt][1]));
            mx1 = fmaxf(mx1, fmaxf(s[nt][2], s[nt][3]));
        }
        mx0 = fmaxf(mx0, __shfl_xor_sync(0xffffffffu, mx0, 1));
        mx0 = fmaxf(mx0, __shfl_xor_sync(0xffffffffu, mx0, 2));
        mx1 = fmaxf(mx1, __shfl_xor_sync(0xffffffffu, mx1, 1));
        mx1 = fmaxf(mx1, __shfl_xor_sync(0xffffffffu, mx1, 2));
        const float alpha0 = __expf(m0 - mx0);
        const float alpha1 = __expf(m1 - mx1);
        m0 = mx0; m1 = mx1;

        uint32_t ph[4][4], pl[4][4];
        float rs0 = 0.f, rs1 = 0.f;
        #pragma unroll
        for (int nt = 0; nt < 8; nt++) {
            float p0 = __expf(s[nt][0] - mx0);
            float p1 = __expf(s[nt][1] - mx0);
            float p2 = __expf(s[nt][2] - mx1);
            float p3 = __expf(s[nt][3] - mx1);
            rs0 += p0 + p1; rs1 += p2 + p3;
            __nv_bfloat162 h01 = __floats2bfloat162_rn(p0, p1);
            __nv_bfloat162 h23 = __floats2bfloat162_rn(p2, p3);
            __nv_bfloat162 l01 = __floats2bfloat162_rn(p0 - __bfloat162float(h01.x),
                                                       p1 - __bfloat162float(h01.y));
            __nv_bfloat162 l23 = __floats2bfloat162_rn(p2 - __bfloat162float(h23.x),
                                                       p3 - __bfloat162float(h23.y));
            const int kt = nt >> 1, hi = (nt & 1) * 2;
            ph[kt][hi + 0] = *(uint32_t*)&h01;
            ph[kt][hi + 1] = *(uint32_t*)&h23;
            pl[kt][hi + 0] = *(uint32_t*)&l01;
            pl[kt][hi + 1] = *(uint32_t*)&l23;
        }
        l0 = l0 * alpha0 + rs0;
        l1 = l1 * alpha1 + rs1;

        #pragma unroll
        for (int nt = 0; nt < 8; nt++) {
            O[nt][0] *= alpha0; O[nt][1] *= alpha0;
            O[nt][2] *= alpha1; O[nt][3] *= alpha1;
        }
        #pragma unroll
        for (int ntp = 0; ntp < 4; ntp++) {
            #pragma unroll
            for (int kt = 0; kt < 4; kt++) {
                uint32_t off = SWZ((ntp * 16 + bn) * 128 + kt * 32 + bkb);
                uint32_t vh0, vh1, vh2, vh3, vl0, vl1, vl2, vl3;
                ldsm_x4(sb + SMB_VH + off, vh0, vh1, vh2, vh3);
                ldsm_x4(sb + SMB_VL + off, vl0, vl1, vl2, vl3);
                float* oa = O[2 * ntp];
                float* oc = O[2 * ntp + 1];
                mma_bf16(oa[0], oa[1], oa[2], oa[3], ph[kt][0], ph[kt][1], ph[kt][2], ph[kt][3], vh0, vh1);
                mma_bf16(oa[0], oa[1], oa[2], oa[3], pl[kt][0], pl[kt][1], pl[kt][2], pl[kt][3], vh0, vh1);
                mma_bf16(oa[0], oa[1], oa[2], oa[3], ph[kt][0], ph[kt][1], ph[kt][2], ph[kt][3], vl0, vl1);
                mma_bf16(oc[0], oc[1], oc[2], oc[3], ph[kt][0], ph[kt][1], ph[kt][2], ph[kt][3], vh2, vh3);
                mma_bf16(oc[0], oc[1], oc[2], oc[3], pl[kt][0], pl[kt][1], pl[kt][2], pl[kt][3], vh2, vh3);
                mma_bf16(oc[0], oc[1], oc[2], oc[3], ph[kt][0], ph[kt][1], ph[kt][2], ph[kt][3], vl2, vl3);
            }
        }
    }

    l0 += __shfl_xor_sync(0xffffffffu, l0, 1);
    l0 += __shfl_xor_sync(0xffffffffu, l0, 2);
    l1 += __shfl_xor_sync(0xffffffffu, l1, 1);
    l1 += __shfl_xor_sync(0xffffffffu, l1, 2);
    const float inv0 = 1.f / l0, inv1 = 1.f / l1;
    const int r = l >> 2, cc = (l & 3) * 2;
    const size_t off0 = (size_t)(q0 + w * 16 + r)     * DIM + head * HD;
    const size_t off1 = (size_t)(q0 + w * 16 + r + 8) * DIM + head * HD;
    #pragma unroll
    for (int nt = 0; nt < 8; nt++) {
        float v00 = O[nt][0] * inv0, v01 = O[nt][1] * inv0;
        float v10 = O[nt][2] * inv1, v11 = O[nt][3] * inv1;
        __nv_bfloat162 h0 = __floats2bfloat162_rn(v00, v01);
        __nv_bfloat162 l0b = __floats2bfloat162_rn(v00 - __bfloat162float(h0.x),
                                                   v01 - __bfloat162float(h0.y));
        __nv_bfloat162 h1 = __floats2bfloat162_rn(v10, v11);
        __nv_bfloat162 l1b = __floats2bfloat162_rn(v10 - __bfloat162float(h1.x),
                                                   v11 - __bfloat162float(h1.y));
        *(__nv_bfloat162*)(g_ctxh + off0 + nt * 8 + cc) = h0;
        *(__nv_bfloat162*)(g_ctxl + off0 + nt * 8 + cc) = l0b;
        *(__nv_bfloat162*)(g_ctxh + off1 + nt * 8 + cc) = h1;
        *(__nv_bfloat162*)(g_ctxl + off1 + nt * 8 + cc) = l1b;
    }
}

// ---------------------------------------------------------------------------
extern "C" void kernel_launch(void* const* d_in, const int* in_sizes, int n_in,
                              void* d_out, int out_size)
{
    const float* x  = (const float*)d_in[0];
    const float* Wq = (const float*)d_in[1];
    const float* bq = (const float*)d_in[2];
    const float* Wk = (const float*)d_in[3];
    const float* bk = (const float*)d_in[4];
    const float* Wv = (const float*)d_in[5];
    const float* bv = (const float*)d_in[6];
    const float* Wo = (const float*)d_in[7];
    const float* bo = (const float*)d_in[8];
    float* out = (float*)d_out;

    float* Vf;
    cudaGetSymbolAddress((void**)&Vf, g_V);
    __nv_bfloat16 *xh, *xl, *Wqh, *Wql, *Wkh, *Wkl, *Wvh, *Wvl, *Woh, *Wol;
    __nv_bfloat16 *Qh, *Ql, *Kh, *Kl, *ctxh, *ctxl;
    cudaGetSymbolAddress((void**)&xh,  g_xh);
    cudaGetSymbolAddress((void**)&xl,  g_xl);
    cudaGetSymbolAddress((void**)&Wqh, g_Wqh);
    cudaGetSymbolAddress((void**)&Wql, g_Wql);
    cudaGetSymbolAddress((void**)&Wkh, g_Wkh);
    cudaGetSymbolAddress((void**)&Wkl, g_Wkl);
    cudaGetSymbolAddress((void**)&Wvh, g_Wvh);
    cudaGetSymbolAddress((void**)&Wvl, g_Wvl);
    cudaGetSymbolAddress((void**)&Woh, g_Woh);
    cudaGetSymbolAddress((void**)&Wol, g_Wol);
    cudaGetSymbolAddress((void**)&Qh,  g_Qh);
    cudaGetSymbolAddress((void**)&Ql,  g_Ql);
    cudaGetSymbolAddress((void**)&Kh,  g_Kh);
    cudaGetSymbolAddress((void**)&Kl,  g_Kl);
    cudaGetSymbolAddress((void**)&ctxh, g_ctxh);
    cudaGetSymbolAddress((void**)&ctxl, g_ctxl);

    // one-time hi/lo conversions
    convert_hl_kernel<<<512, 256>>>(x,  xh,  xl,  1.f, SEQ * DIM);
    convert_hl_kernel<<<128, 256>>>(Wq, Wqh, Wql, 1.f, DIM * DIM);
    convert_hl_kernel<<<128, 256>>>(Wk, Wkh, Wkl, 1.f, DIM * DIM);
    convert_hl_kernel<<<128, 256>>>(Wv, Wvh, Wvl, 1.f, DIM * DIM);
    convert_hl_kernel<<<128, 256>>>(Wo, Woh, Wol, 1.f, DIM * DIM);

    cudaFuncSetAttribute(gemm_tc_kernel,
                         cudaFuncAttributeMaxDynamicSharedMemorySize, GSMEM);
    dim3 ggrid(DIM / 64, SEQ / 128);   // (8, 32)

    // Q/K: fused bias (+0.125 scale for Q) + hi/lo split epilogue
    gemm_tc_kernel<<<ggrid, 256, GSMEM>>>(xh, xl, Wqh, Wql, bq,
                                          nullptr, Qh, Ql, 0.125f, 1);
    gemm_tc_kernel<<<ggrid, 256, GSMEM>>>(xh, xl, Wkh, Wkl, bk,
                                          nullptr, Kh, Kl, 1.f, 1);
    // V: fp32 out, then per-head transpose + split
    gemm_tc_kernel<<<ggrid, 256, GSMEM>>>(xh, xl, Wvh, Wvl, bv,
                                          Vf, nullptr, nullptr, 1.f, 0);
    convert_vt_kernel<<<dim3(SEQ / 64, NH), 256>>>();

    attn_mma_kernel<<<dim3(SEQ / 128, NH), 256, SMB_TOTAL>>>();

    // output projection: consumes ctx hi/lo written by attention
    gemm_tc_kernel<<<ggrid, 256, GSMEM>>>(ctxh, ctxl, Woh, Wol, bo,
                                          out, nullptr, nullptr, 1.f, 0);
}

// round 5
// speedup vs baseline: 4.6608x; 1.2226x over previous
#include <cuda_runtime.h>
#include <cuda_bf16.h>
#include <math.h>
#include <cstdint>

// Problem constants
#define SEQ   4096
#define DIM   512
#define NH    8
#define HD    64

// ---------------------------------------------------------------------------
// Scratch (allocation-free rule: __device__ globals)
// ---------------------------------------------------------------------------
__device__ __nv_bfloat16 g_xh[SEQ * DIM];
__device__ __nv_bfloat16 g_xl[SEQ * DIM];
__device__ __nv_bfloat16 g_Wqh[DIM * DIM], g_Wql[DIM * DIM];
__device__ __nv_bfloat16 g_Wkh[DIM * DIM], g_Wkl[DIM * DIM];
__device__ __nv_bfloat16 g_Wvh[DIM * DIM], g_Wvl[DIM * DIM];
__device__ __nv_bfloat16 g_Woh[DIM * DIM], g_Wol[DIM * DIM];

__device__ __nv_bfloat16 g_Qh[SEQ * DIM];
__device__ __nv_bfloat16 g_Ql[SEQ * DIM];
__device__ __nv_bfloat16 g_Kh[SEQ * DIM];
__device__ __nv_bfloat16 g_Kl[SEQ * DIM];
// V transposed per head: [head][hd=64][seq=4096]
__device__ __nv_bfloat16 g_Vth[NH * HD * SEQ];
__device__ __nv_bfloat16 g_Vtl[NH * HD * SEQ];
// attention output, bf16 hi/lo split (feeds final GEMM)
__device__ __nv_bfloat16 g_ctxh[SEQ * DIM];
__device__ __nv_bfloat16 g_ctxl[SEQ * DIM];

// ---------------------------------------------------------------------------
// warp-mma helpers (baseline PTX: sm_80 mma.sync + sm_75 ldmatrix + cp.async)
// ---------------------------------------------------------------------------
__device__ __forceinline__ uint32_t smem_to_u32(const void* p) {
    uint32_t a;
    asm("{ .reg .u64 t; cvta.to.shared.u64 t, %1; cvt.u32.u64 %0, t; }"
        : "=r"(a) : "l"(p));
    return a;
}

#define SWZ(b) ((b) ^ (((b) >> 3) & 0x70))

__device__ __forceinline__ void ldsm_x4(uint32_t addr, uint32_t& r0, uint32_t& r1,
                                        uint32_t& r2, uint32_t& r3) {
    asm volatile("ldmatrix.sync.aligned.m8n8.x4.shared.b16 {%0,%1,%2,%3}, [%4];"
                 : "=r"(r0), "=r"(r1), "=r"(r2), "=r"(r3) : "r"(addr));
}

__device__ __forceinline__ void mma_bf16(float& d0, float& d1, float& d2, float& d3,
                                         uint32_t a0, uint32_t a1, uint32_t a2, uint32_t a3,
                                         uint32_t b0, uint32_t b1) {
    asm volatile("mma.sync.aligned.m16n8k16.row.col.f32.bf16.bf16.f32 "
                 "{%0,%1,%2,%3}, {%4,%5,%6,%7}, {%8,%9}, {%0,%1,%2,%3};"
                 : "+f"(d0), "+f"(d1), "+f"(d2), "+f"(d3)
                 : "r"(a0), "r"(a1), "r"(a2), "r"(a3), "r"(b0), "r"(b1));
}

__device__ __forceinline__ void cp16(uint32_t dst, const void* src) {
    asm volatile("cp.async.cg.shared.global [%0], [%1], 16;" :: "r"(dst), "l"(src));
}
#define CP_COMMIT() asm volatile("cp.async.commit_group;" ::: "memory")
template <int N>
__device__ __forceinline__ void cp_wait() {
    asm volatile("cp.async.wait_group %0;" :: "n"(N) : "memory");
}

// ---------------------------------------------------------------------------
// Fused fp32 -> bf16 hi/lo conversion for x + all 4 weights (one launch)
// ---------------------------------------------------------------------------
#define NX (SEQ * DIM)
#define NW (DIM * DIM)
__global__ void convert_all_kernel(const float* __restrict__ x,
                                   const float* __restrict__ Wq,
                                   const float* __restrict__ Wk,
                                   const float* __restrict__ Wv,
                                   const float* __restrict__ Wo)
{
    const int total4 = (NX + 4 * NW) / 4;
    int i4 = blockIdx.x * blockDim.x + threadIdx.x;
    const int stride = gridDim.x * blockDim.x;
    for (; i4 < total4; i4 += stride) {
        int idx = i4 * 4;
        const float* src;
        __nv_bfloat16 *dh, *dl;
        int off;
        if (idx < NX)                { src = x;  dh = g_xh;  dl = g_xl;  off = idx; }
        else if (idx < NX + NW)      { src = Wq; dh = g_Wqh; dl = g_Wql; off = idx - NX; }
        else if (idx < NX + 2 * NW)  { src = Wk; dh = g_Wkh; dl = g_Wkl; off = idx - NX - NW; }
        else if (idx < NX + 3 * NW)  { src = Wv; dh = g_Wvh; dl = g_Wvl; off = idx - NX - 2 * NW; }
        else                         { src = Wo; dh = g_Woh; dl = g_Wol; off = idx - NX - 3 * NW; }
        float4 v = *(const float4*)(src + off);
        __nv_bfloat162 h01 = __floats2bfloat162_rn(v.x, v.y);
        __nv_bfloat162 h23 = __floats2bfloat162_rn(v.z, v.w);
        __nv_bfloat162 l01 = __floats2bfloat162_rn(v.x - __bfloat162float(h01.x),
                                                   v.y - __bfloat162float(h01.y));
        __nv_bfloat162 l23 = __floats2bfloat162_rn(v.z - __bfloat162float(h23.x),
                                                   v.w - __bfloat162float(h23.y));
        *(__nv_bfloat162*)(dh + off)     = h01;
        *(__nv_bfloat162*)(dh + off + 2) = h23;
        *(__nv_bfloat162*)(dl + off)     = l01;
        *(__nv_bfloat162*)(dl + off + 2) = l23;
    }
}

// ---------------------------------------------------------------------------
// Tensor-core GEMM: C[M=4096][N=512] = A @ B^T + bias, bf16 hi/lo 3-pass.
// CTA tile 128M x 64N, warps 4(M) x 2(N), warp tile 32x32, cp.async dbl-buffer.
// mode 0: fp32 C.  mode 1: bf16 hi/lo C.  mode 2: bf16 hi/lo, per-head
//         transposed V layout [head][hd][seq] (fused V transpose).
// ---------------------------------------------------------------------------
#define GOFF_AH 0
#define GOFF_AL 16384
#define GOFF_BH 32768
#define GOFF_BL 40960
#define GBUF    49152
#define GSMEM   (2 * GBUF)   // 98304

__device__ __forceinline__ void gemm_stage_chunk(
    uint32_t sbuf,
    const __nv_bfloat16* __restrict__ Ah, const __nv_bfloat16* __restrict__ Al,
    const __nv_bfloat16* __restrict__ Bh, const __nv_bfloat16* __restrict__ Bl,
    int m0, int n0, int k0, int tid)
{
    #pragma unroll
    for (int i = 0; i < 4; i++) {                  // A: 128 rows x 64 cols
        int c = i * 256 + tid;
        int row = c >> 3, col = c & 7;
        uint32_t off = SWZ((uint32_t)(row * 128 + col * 16));
        size_t gidx = (size_t)(m0 + row) * DIM + k0 + col * 8;
        cp16(sbuf + GOFF_AH + off, Ah + gidx);
        cp16(sbuf + GOFF_AL + off, Al + gidx);
    }
    #pragma unroll
    for (int i = 0; i < 2; i++) {                  // B: 64 rows x 64 cols
        int c = i * 256 + tid;
        int row = c >> 3, col = c & 7;
        uint32_t off = SWZ((uint32_t)(row * 128 + col * 16));
        size_t gidx = (size_t)(n0 + row) * DIM + k0 + col * 8;
        cp16(sbuf + GOFF_BH + off, Bh + gidx);
        cp16(sbuf + GOFF_BL + off, Bl + gidx);
    }
}

__global__ __launch_bounds__(256, 2) void gemm_tc_kernel(
    const __nv_bfloat16* __restrict__ Ah, const __nv_bfloat16* __restrict__ Al,
    const __nv_bfloat16* __restrict__ Bh, const __nv_bfloat16* __restrict__ Bl,
    const float* __restrict__ bias,
    float* __restrict__ Cf,
    __nv_bfloat16* __restrict__ Ch, __nv_bfloat16* __restrict__ Cl,
    float scale, int mode)
{
    extern __shared__ char smem[];
    const uint32_t sb = smem_to_u32(smem);
    const int tid = threadIdx.x;
    const int w   = tid >> 5;
    const int l   = tid & 31;
    const int wm  = w & 3;
    const int wn  = w >> 2;
    const int m0  = blockIdx.y * 128;
    const int n0  = blockIdx.x * 64;

    const int qrow = (l & 7) + ((l >> 3) & 1) * 8;
    const int qkb  = ((l >> 4) & 1) * 16;
    const int bn   = (l & 7) + ((l >> 4) & 1) * 8;
    const int bkb  = ((l >> 3) & 1) * 16;

    float acc[2][4][4];
    #pragma unroll
    for (int mf = 0; mf < 2; mf++)
        #pragma unroll
        for (int j = 0; j < 4; j++)
            #pragma unroll
            for (int q = 0; q < 4; q++) acc[mf][j][q] = 0.f;

    gemm_stage_chunk(sb, Ah, Al, Bh, Bl, m0, n0, 0, tid);
    CP_COMMIT();

    for (int ch = 0; ch < 8; ch++) {
        if (ch < 7) {
            gemm_stage_chunk(sb + ((ch + 1) & 1) * GBUF, Ah, Al, Bh, Bl,
                             m0, n0, (ch + 1) * 64, tid);
            CP_COMMIT();
            cp_wait<1>();
        } else {
            cp_wait<0>();
        }
        __syncthreads();

        const uint32_t b = sb + (ch & 1) * GBUF;
        #pragma unroll
        for (int kt = 0; kt < 4; kt++) {
            uint32_t ah[2][4], al[2][4];
            #pragma unroll
            for (int mf = 0; mf < 2; mf++) {
                uint32_t aoff = SWZ((uint32_t)((wm * 32 + mf * 16 + qrow) * 128 + kt * 32 + qkb));
                ldsm_x4(b + GOFF_AH + aoff, ah[mf][0], ah[mf][1], ah[mf][2], ah[mf][3]);
                ldsm_x4(b + GOFF_AL + aoff, al[mf][0], al[mf][1], al[mf][2], al[mf][3]);
            }
            #pragma unroll
            for (int np = 0; np < 2; np++) {
                uint32_t boff = SWZ((uint32_t)((wn * 32 + np * 16 + bn) * 128 + kt * 32 + bkb));
                uint32_t bh0, bh1, bh2, bh3, bl0, bl1, bl2, bl3;
                ldsm_x4(b + GOFF_BH + boff, bh0, bh1, bh2, bh3);
                ldsm_x4(b + GOFF_BL + boff, bl0, bl1, bl2, bl3);
                #pragma unroll
                for (int mf = 0; mf < 2; mf++) {
                    float* a0 = acc[mf][2 * np];
                    float* a1 = acc[mf][2 * np + 1];
                    mma_bf16(a0[0], a0[1], a0[2], a0[3], ah[mf][0], ah[mf][1], ah[mf][2], ah[mf][3], bh0, bh1);
                    mma_bf16(a0[0], a0[1], a0[2], a0[3], al[mf][0], al[mf][1], al[mf][2], al[mf][3], bh0, bh1);
                    mma_bf16(a0[0], a0[1], a0[2], a0[3], ah[mf][0], ah[mf][1], ah[mf][2], ah[mf][3], bl0, bl1);
                    mma_bf16(a1[0], a1[1], a1[2], a1[3], ah[mf][0], ah[mf][1], ah[mf][2], ah[mf][3], bh2, bh3);
                    mma_bf16(a1[0], a1[1], a1[2], a1[3], al[mf][0], al[mf][1], al[mf][2], al[mf][3], bh2, bh3);
                    mma_bf16(a1[0], a1[1], a1[2], a1[3], ah[mf][0], ah[mf][1], ah[mf][2], ah[mf][3], bl2, bl3);
                }
            }
        }
        __syncthreads();
    }

    const int r = l >> 2, cc = (l & 3) * 2;
    #pragma unroll
    for (int mf = 0; mf < 2; mf++) {
        const int mrow = m0 + wm * 32 + mf * 16 + r;
        #pragma unroll
        for (int j = 0; j < 4; j++) {
            const int col = n0 + wn * 32 + (j >> 1) * 16 + (j & 1) * 8 + cc;
            const float b0 = bias[col], b1 = bias[col + 1];
            float v00 = (acc[mf][j][0] + b0) * scale;
            float v01 = (acc[mf][j][1] + b1) * scale;
            float v10 = (acc[mf][j][2] + b0) * scale;
            float v11 = (acc[mf][j][3] + b1) * scale;
            if (mode == 0) {
                *(float2*)&Cf[(size_t)mrow * DIM + col]       = make_float2(v00, v01);
                *(float2*)&Cf[(size_t)(mrow + 8) * DIM + col] = make_float2(v10, v11);
            } else if (mode == 1) {
                __nv_bfloat162 h0 = __floats2bfloat162_rn(v00, v01);
                __nv_bfloat162 l0 = __floats2bfloat162_rn(v00 - __bfloat162float(h0.x),
                                                          v01 - __bfloat162float(h0.y));
                __nv_bfloat162 h1 = __floats2bfloat162_rn(v10, v11);
                __nv_bfloat162 l1 = __floats2bfloat162_rn(v10 - __bfloat162float(h1.x),
                                                          v11 - __bfloat162float(h1.y));
                *(__nv_bfloat162*)&Ch[(size_t)mrow * DIM + col]       = h0;
                *(__nv_bfloat162*)&Cl[(size_t)mrow * DIM + col]       = l0;
                *(__nv_bfloat162*)&Ch[(size_t)(mrow + 8) * DIM + col] = h1;
                *(__nv_bfloat162*)&Cl[(size_t)(mrow + 8) * DIM + col] = l1;
            } else {
                // mode 2: V -> transposed per-head hi/lo [head][hd][seq]
                const int head = col >> 6, hd = col & 63;
                const size_t t0 = (size_t)(head * HD + hd)     * SEQ;
                const size_t t1 = (size_t)(head * HD + hd + 1) * SEQ;
                __nv_bfloat16 h;
                h = __float2bfloat16(v00);
                g_Vth[t0 + mrow] = h; g_Vtl[t0 + mrow] = __float2bfloat16(v00 - __bfloat162float(h));
                h = __float2bfloat16(v01);
                g_Vth[t1 + mrow] = h; g_Vtl[t1 + mrow] = __float2bfloat16(v01 - __bfloat162float(h));
                h = __float2bfloat16(v10);
                g_Vth[t0 + mrow + 8] = h; g_Vtl[t0 + mrow + 8] = __float2bfloat16(v10 - __bfloat162float(h));
                h = __float2bfloat16(v11);
                g_Vth[t1 + mrow + 8] = h; g_Vtl[t1 + mrow + 8] = __float2bfloat16(v11 - __bfloat162float(h));
            }
        }
    }
}

// ---------------------------------------------------------------------------
// Flash attention via mma.sync bf16 hi/lo (3-pass), cp.async double-buffered.
// CTA: 128 q-rows x head, 256 threads = 8 warps, each warp 16 q-rows.
// Q hi/lo resident in smem (re-ldmatrix per k-tile); occupancy 2 target.
// ---------------------------------------------------------------------------
#define AQ_H   0
#define AQ_L   16384
#define ABUF0  32768
#define ABUF_SZ 32768
#define A_KH   0
#define A_KL   8192
#define A_VH   16384
#define A_VL   24576
#define ASMEM  (ABUF0 + 2 * ABUF_SZ)   // 98304

__device__ __forceinline__ void attn_stage_kv(uint32_t sbuf, int head, int kv0, int tid)
{
    #pragma unroll
    for (int i = 0; i < 2; i++) {
        int c = i * 256 + tid;               // 512 chunks per 8KB tile
        int row = c >> 3, col = c & 7;
        uint32_t off = SWZ((uint32_t)(row * 128 + col * 16));
        size_t gk = (size_t)(kv0 + row) * DIM + head * HD + col * 8;
        cp16(sbuf + A_KH + off, g_Kh + gk);
        cp16(sbuf + A_KL + off, g_Kl + gk);
        size_t gv = (size_t)(head * HD + row) * SEQ + kv0 + col * 8;
        cp16(sbuf + A_VH + off, g_Vth + gv);
        cp16(sbuf + A_VL + off, g_Vtl + gv);
    }
}

__global__ __launch_bounds__(256, 2) void attn_mma_kernel()
{
    extern __shared__ char smem[];
    const uint32_t sb = smem_to_u32(smem);
    const int tid  = threadIdx.x;
    const int w    = tid >> 5;
    const int l    = tid & 31;
    const int head = blockIdx.y;
    const int q0   = blockIdx.x * 128;

    const int qrow = (l & 7) + ((l >> 3) & 1) * 8;
    const int qkb  = ((l >> 4) & 1) * 16;
    const int bn   = (l & 7) + ((l >> 4) & 1) * 8;
    const int bkb  = ((l >> 3) & 1) * 16;

    // stage Q (128x64 hi/lo) via cp.async
    #pragma unroll
    for (int i = 0; i < 4; i++) {
        int c = i * 256 + tid;
        int row = c >> 3, col = c & 7;
        uint32_t off = SWZ((uint32_t)(row * 128 + col * 16));
        size_t gq = (size_t)(q0 + row) * DIM + head * HD + col * 8;
        cp16(sb + AQ_H + off, g_Qh + gq);
        cp16(sb + AQ_L + off, g_Ql + gq);
    }
    attn_stage_kv(sb + ABUF0, head, 0, tid);
    CP_COMMIT();

    float m0 = -1e30f, m1 = -1e30f;
    float l0 = 0.f, l1 = 0.f;
    float O[8][4];
    #pragma unroll
    for (int nt = 0; nt < 8; nt++)
        #pragma unroll
        for (int j = 0; j < 4; j++) O[nt][j] = 0.f;

    for (int it = 0; it < SEQ / 64; ++it) {
        if (it < SEQ / 64 - 1) {
            attn_stage_kv(sb + ABUF0 + ((it + 1) & 1) * ABUF_SZ, head, (it + 1) * 64, tid);
            CP_COMMIT();
            cp_wait<1>();
        } else {
            cp_wait<0>();
        }
        __syncthreads();

        const uint32_t buf = sb + ABUF0 + (it & 1) * ABUF_SZ;

        // ---- S = Q K^T (hi/lo 3-pass) ----
        float s[8][4];
        #pragma unroll
        for (int nt = 0; nt < 8; nt++)
            #pragma unroll
            for (int j = 0; j < 4; j++) s[nt][j] = 0.f;

        #pragma unroll
        for (int kt = 0; kt < 4; kt++) {
            uint32_t qoff = SWZ((uint32_t)((w * 16 + qrow) * 128 + kt * 32 + qkb));
            uint32_t qh0, qh1, qh2, qh3, ql0, ql1, ql2, ql3;
            ldsm_x4(sb + AQ_H + qoff, qh0, qh1, qh2, qh3);
            ldsm_x4(sb + AQ_L + qoff, ql0, ql1, ql2, ql3);
            #pragma unroll
            for (int ntp = 0; ntp < 4; ntp++) {
                uint32_t off = SWZ((uint32_t)((ntp * 16 + bn) * 128 + kt * 32 + bkb));
                uint32_t kh0, kh1, kh2, kh3, kl0, kl1, kl2, kl3;
                ldsm_x4(buf + A_KH + off, kh0, kh1, kh2, kh3);
                ldsm_x4(buf + A_KL + off, kl0, kl1, kl2, kl3);
                float* sa = s[2 * ntp];
                float* sc = s[2 * ntp + 1];
                mma_bf16(sa[0], sa[1], sa[2], sa[3], qh0, qh1, qh2, qh3, kh0, kh1);
                mma_bf16(sa[0], sa[1], sa[2], sa[3], ql0, ql1, ql2, ql3, kh0, kh1);
                mma_bf16(sa[0], sa[1], sa[2], sa[3], qh0, qh1, qh2, qh3, kl0, kl1);
                mma_bf16(sc[0], sc[1], sc[2], sc[3], qh0, qh1, qh2, qh3, kh2, kh3);
                mma_bf16(sc[0], sc[1], sc[2], sc[3], ql0, ql1, ql2, ql3, kh2, kh3);
                mma_bf16(sc[0], sc[1], sc[2], sc[3], qh0, qh1, qh2, qh3, kl2, kl3);
            }
        }

        // ---- online softmax ----
        float mx0 = m0, mx1 = m1;
        #pragma unroll
        for (int nt = 0; nt < 8; nt++) {
            mx0 = fmaxf(mx0, fmaxf(s[nt][0], s[nt][1]));
            mx1 = fmaxf(mx1, fmaxf(s[nt][2], s[nt][3]));
        }
        mx0 = fmaxf(mx0, __shfl_xor_sync(0xffffffffu, mx0, 1));
        mx0 = fmaxf(mx0, __shfl_xor_sync(0xffffffffu, mx0, 2));
        mx1 = fmaxf(mx1, __shfl_xor_sync(0xffffffffu, mx1, 1));
        mx1 = fmaxf(mx1, __shfl_xor_sync(0xffffffffu, mx1, 2));
        const float alpha0 = __expf(m0 - mx0);
        const float alpha1 = __expf(m1 - mx1);
        m0 = mx0; m1 = mx1;

        uint32_t ph[4][4], pl[4][4];
        float rs0 = 0.f, rs1 = 0.f;
        #pragma unroll
        for (int nt = 0; nt < 8; nt++) {
            float p0 = __expf(s[nt][0] - mx0);
            float p1 = __expf(s[nt][1] - mx0);
            float p2 = __expf(s[nt][2] - mx1);
            float p3 = __expf(s[nt][3] - mx1);
            rs0 += p0 + p1; rs1 += p2 + p3;
            __nv_bfloat162 h01 = __floats2bfloat162_rn(p0, p1);
            __nv_bfloat162 h23 = __floats2bfloat162_rn(p2, p3);
            __nv_bfloat162 l01 = __floats2bfloat162_rn(p0 - __bfloat162float(h01.x),
                                                       p1 - __bfloat162float(h01.y));
            __nv_bfloat162 l23 = __floats2bfloat162_rn(p2 - __bfloat162float(h23.x),
                                                       p3 - __bfloat162float(h23.y));
            const int kt = nt >> 1, hi = (nt & 1) * 2;
            ph[kt][hi + 0] = *(uint32_t*)&h01;
            ph[kt][hi + 1] = *(uint32_t*)&h23;
            pl[kt][hi + 0] = *(uint32_t*)&l01;
            pl[kt][hi + 1] = *(uint32_t*)&l23;
        }
        l0 = l0 * alpha0 + rs0;
        l1 = l1 * alpha1 + rs1;

        #pragma unroll
        for (int nt = 0; nt < 8; nt++) {
            O[nt][0] *= alpha0; O[nt][1] *= alpha0;
            O[nt][2] *= alpha1; O[nt][3] *= alpha1;
        }

        // ---- O += P @ V (hi/lo 3-pass) ----
        #pragma unroll
        for (int ntp = 0; ntp < 4; ntp++) {
            #pragma unroll
            for (int kt = 0; kt < 4; kt++) {
                uint32_t off = SWZ((uint32_t)((ntp * 16 + bn) * 128 + kt * 32 + bkb));
                uint32_t vh0, vh1, vh2, vh3, vl0, vl1, vl2, vl3;
                ldsm_x4(buf + A_VH + off, vh0, vh1, vh2, vh3);
                ldsm_x4(buf + A_VL + off, vl0, vl1, vl2, vl3);
                float* oa = O[2 * ntp];
                float* oc = O[2 * ntp + 1];
                mma_bf16(oa[0], oa[1], oa[2], oa[3], ph[kt][0], ph[kt][1], ph[kt][2], ph[kt][3], vh0, vh1);
                mma_bf16(oa[0], oa[1], oa[2], oa[3], pl[kt][0], pl[kt][1], pl[kt][2], pl[kt][3], vh0, vh1);
                mma_bf16(oa[0], oa[1], oa[2], oa[3], ph[kt][0], ph[kt][1], ph[kt][2], ph[kt][3], vl0, vl1);
                mma_bf16(oc[0], oc[1], oc[2], oc[3], ph[kt][0], ph[kt][1], ph[kt][2], ph[kt][3], vh2, vh3);
                mma_bf16(oc[0], oc[1], oc[2], oc[3], pl[kt][0], pl[kt][1], pl[kt][2], pl[kt][3], vh2, vh3);
                mma_bf16(oc[0], oc[1], oc[2], oc[3], ph[kt][0], ph[kt][1], ph[kt][2], ph[kt][3], vl2, vl3);
            }
        }
        __syncthreads();   // all reads of buf done before it is restaged
    }

    l0 += __shfl_xor_sync(0xffffffffu, l0, 1);
    l0 += __shfl_xor_sync(0xffffffffu, l0, 2);
    l1 += __shfl_xor_sync(0xffffffffu, l1, 1);
    l1 += __shfl_xor_sync(0xffffffffu, l1, 2);
    const float inv0 = 1.f / l0, inv1 = 1.f / l1;
    const int r = l >> 2, cc = (l & 3) * 2;
    const size_t off0 = (size_t)(q0 + w * 16 + r)     * DIM + head * HD;
    const size_t off1 = (size_t)(q0 + w * 16 + r + 8) * DIM + head * HD;
    #pragma unroll
    for (int nt = 0; nt < 8; nt++) {
        float v00 = O[nt][0] * inv0, v01 = O[nt][1] * inv0;
        float v10 = O[nt][2] * inv1, v11 = O[nt][3] * inv1;
        __nv_bfloat162 h0 = __floats2bfloat162_rn(v00, v01);
        __nv_bfloat162 l0b = __floats2bfloat162_rn(v00 - __bfloat162float(h0.x),
                                                   v01 - __bfloat162float(h0.y));
        __nv_bfloat162 h1 = __floats2bfloat162_rn(v10, v11);
        __nv_bfloat162 l1b = __floats2bfloat162_rn(v10 - __bfloat162float(h1.x),
                                                   v11 - __bfloat162float(h1.y));
        *(__nv_bfloat162*)(g_ctxh + off0 + nt * 8 + cc) = h0;
        *(__nv_bfloat162*)(g_ctxl + off0 + nt * 8 + cc) = l0b;
        *(__nv_bfloat162*)(g_ctxh + off1 + nt * 8 + cc) = h1;
        *(__nv_bfloat162*)(g_ctxl + off1 + nt * 8 + cc) = l1b;
    }
}

// ---------------------------------------------------------------------------
extern "C" void kernel_launch(void* const* d_in, const int* in_sizes, int n_in,
                              void* d_out, int out_size)
{
    const float* x  = (const float*)d_in[0];
    const float* Wq = (const float*)d_in[1];
    const float* bq = (const float*)d_in[2];
    const float* Wk = (const float*)d_in[3];
    const float* bk = (const float*)d_in[4];
    const float* Wv = (const float*)d_in[5];
    const float* bv = (const float*)d_in[6];
    const float* Wo = (const float*)d_in[7];
    const float* bo = (const float*)d_in[8];
    float* out = (float*)d_out;

    __nv_bfloat16 *xh, *xl, *Wqh, *Wql, *Wkh, *Wkl, *Wvh, *Wvl, *Woh, *Wol;
    __nv_bfloat16 *Qh, *Ql, *Kh, *Kl, *ctxh, *ctxl;
    cudaGetSymbolAddress((void**)&xh,  g_xh);
    cudaGetSymbolAddress((void**)&xl,  g_xl);
    cudaGetSymbolAddress((void**)&Wqh, g_Wqh);
    cudaGetSymbolAddress((void**)&Wql, g_Wql);
    cudaGetSymbolAddress((void**)&Wkh, g_Wkh);
    cudaGetSymbolAddress((void**)&Wkl, g_Wkl);
    cudaGetSymbolAddress((void**)&Wvh, g_Wvh);
    cudaGetSymbolAddress((void**)&Wvl, g_Wvl);
    cudaGetSymbolAddress((void**)&Woh, g_Woh);
    cudaGetSymbolAddress((void**)&Wol, g_Wol);
    cudaGetSymbolAddress((void**)&Qh,  g_Qh);
    cudaGetSymbolAddress((void**)&Ql,  g_Ql);
    cudaGetSymbolAddress((void**)&Kh,  g_Kh);
    cudaGetSymbolAddress((void**)&Kl,  g_Kl);
    cudaGetSymbolAddress((void**)&ctxh, g_ctxh);
    cudaGetSymbolAddress((void**)&ctxl, g_ctxl);

    convert_all_kernel<<<1536, 256>>>(x, Wq, Wk, Wv, Wo);

    cudaFuncSetAttribute(gemm_tc_kernel,
                         cudaFuncAttributeMaxDynamicSharedMemorySize, GSMEM);
    dim3 ggrid(DIM / 64, SEQ / 128);   // (8, 32)

    gemm_tc_kernel<<<ggrid, 256, GSMEM>>>(xh, xl, Wqh, Wql, bq,
                                          nullptr, Qh, Ql, 0.125f, 1);
    gemm_tc_kernel<<<ggrid, 256, GSMEM>>>(xh, xl, Wkh, Wkl, bk,
                                          nullptr, Kh, Kl, 1.f, 1);
    gemm_tc_kernel<<<ggrid, 256, GSMEM>>>(xh, xl, Wvh, Wvl, bv,
                                          nullptr, nullptr, nullptr, 1.f, 2);

    cudaFuncSetAttribute(attn_mma_kernel,
                         cudaFuncAttributeMaxDynamicSharedMemorySize, ASMEM);
    attn_mma_kernel<<<dim3(SEQ / 128, NH), 256, ASMEM>>>();

    gemm_tc_kernel<<<ggrid, 256, GSMEM>>>(ctxh, ctxl, Woh, Wol, bo,
                                          out, nullptr, nullptr, 1.f, 0);
}

// round 6
// speedup vs baseline: 4.6624x; 1.0003x over previous
#include <cuda_runtime.h>
#include <cuda_bf16.h>
#include <math.h>
#include <cstdint>

// Problem constants
#define SEQ   4096
#define DIM   512
#define NH    8
#define HD    64

// ---------------------------------------------------------------------------
// Scratch (allocation-free rule: __device__ globals)
// ---------------------------------------------------------------------------
__device__ __nv_bfloat16 g_xh[SEQ * DIM];
__device__ __nv_bfloat16 g_xl[SEQ * DIM];
__device__ __nv_bfloat16 g_Wqh[DIM * DIM], g_Wql[DIM * DIM];
__device__ __nv_bfloat16 g_Wkh[DIM * DIM], g_Wkl[DIM * DIM];
__device__ __nv_bfloat16 g_Wvh[DIM * DIM], g_Wvl[DIM * DIM];
__device__ __nv_bfloat16 g_Woh[DIM * DIM], g_Wol[DIM * DIM];

__device__ __nv_bfloat16 g_Qh[SEQ * DIM];
__device__ __nv_bfloat16 g_Ql[SEQ * DIM];
__device__ __nv_bfloat16 g_Kh[SEQ * DIM];
__device__ __nv_bfloat16 g_Kl[SEQ * DIM];
// V transposed per head: [head][hd=64][seq=4096]
__device__ __nv_bfloat16 g_Vth[NH * HD * SEQ];
__device__ __nv_bfloat16 g_Vtl[NH * HD * SEQ];
// attention output, bf16 hi/lo split (feeds final GEMM)
__device__ __nv_bfloat16 g_ctxh[SEQ * DIM];
__device__ __nv_bfloat16 g_ctxl[SEQ * DIM];

// ---------------------------------------------------------------------------
// warp-mma helpers (baseline PTX: sm_80 mma.sync + sm_75 ldmatrix + cp.async)
// ---------------------------------------------------------------------------
__device__ __forceinline__ uint32_t smem_to_u32(const void* p) {
    uint32_t a;
    asm("{ .reg .u64 t; cvta.to.shared.u64 t, %1; cvt.u32.u64 %0, t; }"
        : "=r"(a) : "l"(p));
    return a;
}

#define SWZ(b) ((b) ^ (((b) >> 3) & 0x70))

__device__ __forceinline__ void ldsm_x4(uint32_t addr, uint32_t& r0, uint32_t& r1,
                                        uint32_t& r2, uint32_t& r3) {
    asm volatile("ldmatrix.sync.aligned.m8n8.x4.shared.b16 {%0,%1,%2,%3}, [%4];"
                 : "=r"(r0), "=r"(r1), "=r"(r2), "=r"(r3) : "r"(addr));
}

// NOTE: non-volatile — pure register op; lets ptxas interleave independent
// MMA chains and hide HMMA latency.
__device__ __forceinline__ void mma_bf16(float& d0, float& d1, float& d2, float& d3,
                                         uint32_t a0, uint32_t a1, uint32_t a2, uint32_t a3,
                                         uint32_t b0, uint32_t b1) {
    asm("mma.sync.aligned.m16n8k16.row.col.f32.bf16.bf16.f32 "
        "{%0,%1,%2,%3}, {%4,%5,%6,%7}, {%8,%9}, {%0,%1,%2,%3};"
        : "+f"(d0), "+f"(d1), "+f"(d2), "+f"(d3)
        : "r"(a0), "r"(a1), "r"(a2), "r"(a3), "r"(b0), "r"(b1));
}

__device__ __forceinline__ void cp16(uint32_t dst, const void* src) {
    asm volatile("cp.async.cg.shared.global [%0], [%1], 16;" :: "r"(dst), "l"(src));
}
#define CP_COMMIT() asm volatile("cp.async.commit_group;" ::: "memory")
template <int N>
__device__ __forceinline__ void cp_wait() {
    asm volatile("cp.async.wait_group %0;" :: "n"(N) : "memory");
}

// ---------------------------------------------------------------------------
// Fused fp32 -> bf16 hi/lo conversion for x + all 4 weights (one launch)
// ---------------------------------------------------------------------------
#define NX (SEQ * DIM)
#define NW (DIM * DIM)
__global__ void convert_all_kernel(const float* __restrict__ x,
                                   const float* __restrict__ Wq,
                                   const float* __restrict__ Wk,
                                   const float* __restrict__ Wv,
                                   const float* __restrict__ Wo)
{
    const int total4 = (NX + 4 * NW) / 4;
    int i4 = blockIdx.x * blockDim.x + threadIdx.x;
    const int stride = gridDim.x * blockDim.x;
    for (; i4 < total4; i4 += stride) {
        int idx = i4 * 4;
        const float* src;
        __nv_bfloat16 *dh, *dl;
        int off;
        if (idx < NX)                { src = x;  dh = g_xh;  dl = g_xl;  off = idx; }
        else if (idx < NX + NW)      { src = Wq; dh = g_Wqh; dl = g_Wql; off = idx - NX; }
        else if (idx < NX + 2 * NW)  { src = Wk; dh = g_Wkh; dl = g_Wkl; off = idx - NX - NW; }
        else if (idx < NX + 3 * NW)  { src = Wv; dh = g_Wvh; dl = g_Wvl; off = idx - NX - 2 * NW; }
        else                         { src = Wo; dh = g_Woh; dl = g_Wol; off = idx - NX - 3 * NW; }
        float4 v = *(const float4*)(src + off);
        __nv_bfloat162 h01 = __floats2bfloat162_rn(v.x, v.y);
        __nv_bfloat162 h23 = __floats2bfloat162_rn(v.z, v.w);
        __nv_bfloat162 l01 = __floats2bfloat162_rn(v.x - __bfloat162float(h01.x),
                                                   v.y - __bfloat162float(h01.y));
        __nv_bfloat162 l23 = __floats2bfloat162_rn(v.z - __bfloat162float(h23.x),
                                                   v.w - __bfloat162float(h23.y));
        *(__nv_bfloat162*)(dh + off)     = h01;
        *(__nv_bfloat162*)(dh + off + 2) = h23;
        *(__nv_bfloat162*)(dl + off)     = l01;
        *(__nv_bfloat162*)(dl + off + 2) = l23;
    }
}

// ---------------------------------------------------------------------------
// Tensor-core GEMM: C[M=4096][N=512] = A @ B^T + bias, bf16 hi/lo 3-pass.
// CTA tile 128M x 64N, warps 4(M) x 2(N), warp tile 32x32, cp.async dbl-buffer.
// mode 0: fp32 C.  mode 1: bf16 hi/lo C.  mode 2: bf16 hi/lo, per-head
//         transposed V layout [head][hd][seq] (fused V transpose).
// ---------------------------------------------------------------------------
#define GOFF_AH 0
#define GOFF_AL 16384
#define GOFF_BH 32768
#define GOFF_BL 40960
#define GBUF    49152
#define GSMEM   (2 * GBUF)   // 98304

__device__ __forceinline__ void gemm_stage_chunk(
    uint32_t sbuf,
    const __nv_bfloat16* __restrict__ Ah, const __nv_bfloat16* __restrict__ Al,
    const __nv_bfloat16* __restrict__ Bh, const __nv_bfloat16* __restrict__ Bl,
    int m0, int n0, int k0, int tid)
{
    #pragma unroll
    for (int i = 0; i < 4; i++) {                  // A: 128 rows x 64 cols
        int c = i * 256 + tid;
        int row = c >> 3, col = c & 7;
        uint32_t off = SWZ((uint32_t)(row * 128 + col * 16));
        size_t gidx = (size_t)(m0 + row) * DIM + k0 + col * 8;
        cp16(sbuf + GOFF_AH + off, Ah + gidx);
        cp16(sbuf + GOFF_AL + off, Al + gidx);
    }
    #pragma unroll
    for (int i = 0; i < 2; i++) {                  // B: 64 rows x 64 cols
        int c = i * 256 + tid;
        int row = c >> 3, col = c & 7;
        uint32_t off = SWZ((uint32_t)(row * 128 + col * 16));
        size_t gidx = (size_t)(n0 + row) * DIM + k0 + col * 8;
        cp16(sbuf + GOFF_BH + off, Bh + gidx);
        cp16(sbuf + GOFF_BL + off, Bl + gidx);
    }
}

__global__ __launch_bounds__(256, 2) void gemm_tc_kernel(
    const __nv_bfloat16* __restrict__ Ah, const __nv_bfloat16* __restrict__ Al,
    const __nv_bfloat16* __restrict__ Bh, const __nv_bfloat16* __restrict__ Bl,
    const float* __restrict__ bias,
    float* __restrict__ Cf,
    __nv_bfloat16* __restrict__ Ch, __nv_bfloat16* __restrict__ Cl,
    float scale, int mode)
{
    extern __shared__ char smem[];
    const uint32_t sb = smem_to_u32(smem);
    const int tid = threadIdx.x;
    const int w   = tid >> 5;
    const int l   = tid & 31;
    const int wm  = w & 3;
    const int wn  = w >> 2;
    const int m0  = blockIdx.y * 128;
    const int n0  = blockIdx.x * 64;

    const int qrow = (l & 7) + ((l >> 3) & 1) * 8;
    const int qkb  = ((l >> 4) & 1) * 16;
    const int bn   = (l & 7) + ((l >> 4) & 1) * 8;
    const int bkb  = ((l >> 3) & 1) * 16;

    float acc[2][4][4];
    #pragma unroll
    for (int mf = 0; mf < 2; mf++)
        #pragma unroll
        for (int j = 0; j < 4; j++)
            #pragma unroll
            for (int q = 0; q < 4; q++) acc[mf][j][q] = 0.f;

    gemm_stage_chunk(sb, Ah, Al, Bh, Bl, m0, n0, 0, tid);
    CP_COMMIT();

    for (int ch = 0; ch < 8; ch++) {
        if (ch < 7) {
            gemm_stage_chunk(sb + ((ch + 1) & 1) * GBUF, Ah, Al, Bh, Bl,
                             m0, n0, (ch + 1) * 64, tid);
            CP_COMMIT();
            cp_wait<1>();
        } else {
            cp_wait<0>();
        }
        __syncthreads();

        const uint32_t b = sb + (ch & 1) * GBUF;
        #pragma unroll
        for (int kt = 0; kt < 4; kt++) {
            uint32_t ah[2][4], al[2][4];
            #pragma unroll
            for (int mf = 0; mf < 2; mf++) {
                uint32_t aoff = SWZ((uint32_t)((wm * 32 + mf * 16 + qrow) * 128 + kt * 32 + qkb));
                ldsm_x4(b + GOFF_AH + aoff, ah[mf][0], ah[mf][1], ah[mf][2], ah[mf][3]);
                ldsm_x4(b + GOFF_AL + aoff, al[mf][0], al[mf][1], al[mf][2], al[mf][3]);
            }
            #pragma unroll
            for (int np = 0; np < 2; np++) {
                uint32_t boff = SWZ((uint32_t)((wn * 32 + np * 16 + bn) * 128 + kt * 32 + bkb));
                uint32_t bh0, bh1, bh2, bh3, bl0, bl1, bl2, bl3;
                ldsm_x4(b + GOFF_BH + boff, bh0, bh1, bh2, bh3);
                ldsm_x4(b + GOFF_BL + boff, bl0, bl1, bl2, bl3);
                #pragma unroll
                for (int mf = 0; mf < 2; mf++) {
                    float* a0 = acc[mf][2 * np];
                    float* a1 = acc[mf][2 * np + 1];
                    // interleaved emission: alternate independent accumulators
                    mma_bf16(a0[0], a0[1], a0[2], a0[3], ah[mf][0], ah[mf][1], ah[mf][2], ah[mf][3], bh0, bh1);
                    mma_bf16(a1[0], a1[1], a1[2], a1[3], ah[mf][0], ah[mf][1], ah[mf][2], ah[mf][3], bh2, bh3);
                    mma_bf16(a0[0], a0[1], a0[2], a0[3], al[mf][0], al[mf][1], al[mf][2], al[mf][3], bh0, bh1);
                    mma_bf16(a1[0], a1[1], a1[2], a1[3], al[mf][0], al[mf][1], al[mf][2], al[mf][3], bh2, bh3);
                    mma_bf16(a0[0], a0[1], a0[2], a0[3], ah[mf][0], ah[mf][1], ah[mf][2], ah[mf][3], bl0, bl1);
                    mma_bf16(a1[0], a1[1], a1[2], a1[3], ah[mf][0], ah[mf][1], ah[mf][2], ah[mf][3], bl2, bl3);
                }
            }
        }
        __syncthreads();
    }

    const int r = l >> 2, cc = (l & 3) * 2;
    #pragma unroll
    for (int mf = 0; mf < 2; mf++) {
        const int mrow = m0 + wm * 32 + mf * 16 + r;
        #pragma unroll
        for (int j = 0; j < 4; j++) {
            const int col = n0 + wn * 32 + (j >> 1) * 16 + (j & 1) * 8 + cc;
            const float b0 = bias[col], b1 = bias[col + 1];
            float v00 = (acc[mf][j][0] + b0) * scale;
            float v01 = (acc[mf][j][1] + b1) * scale;
            float v10 = (acc[mf][j][2] + b0) * scale;
            float v11 = (acc[mf][j][3] + b1) * scale;
            if (mode == 0) {
                *(float2*)&Cf[(size_t)mrow * DIM + col]       = make_float2(v00, v01);
                *(float2*)&Cf[(size_t)(mrow + 8) * DIM + col] = make_float2(v10, v11);
            } else if (mode == 1) {
                __nv_bfloat162 h0 = __floats2bfloat162_rn(v00, v01);
                __nv_bfloat162 l0 = __floats2bfloat162_rn(v00 - __bfloat162float(h0.x),
                                                          v01 - __bfloat162float(h0.y));
                __nv_bfloat162 h1 = __floats2bfloat162_rn(v10, v11);
                __nv_bfloat162 l1 = __floats2bfloat162_rn(v10 - __bfloat162float(h1.x),
                                                          v11 - __bfloat162float(h1.y));
                *(__nv_bfloat162*)&Ch[(size_t)mrow * DIM + col]       = h0;
                *(__nv_bfloat162*)&Cl[(size_t)mrow * DIM + col]       = l0;
                *(__nv_bfloat162*)&Ch[(size_t)(mrow + 8) * DIM + col] = h1;
                *(__nv_bfloat162*)&Cl[(size_t)(mrow + 8) * DIM + col] = l1;
            } else {
                // mode 2: V -> transposed per-head hi/lo [head][hd][seq]
                const int head = col >> 6, hd = col & 63;
                const size_t t0 = (size_t)(head * HD + hd)     * SEQ;
                const size_t t1 = (size_t)(head * HD + hd + 1) * SEQ;
                __nv_bfloat16 h;
                h = __float2bfloat16(v00);
                g_Vth[t0 + mrow] = h; g_Vtl[t0 + mrow] = __float2bfloat16(v00 - __bfloat162float(h));
                h = __float2bfloat16(v01);
                g_Vth[t1 + mrow] = h; g_Vtl[t1 + mrow] = __float2bfloat16(v01 - __bfloat162float(h));
                h = __float2bfloat16(v10);
                g_Vth[t0 + mrow + 8] = h; g_Vtl[t0 + mrow + 8] = __float2bfloat16(v10 - __bfloat162float(h));
                h = __float2bfloat16(v11);
                g_Vth[t1 + mrow + 8] = h; g_Vtl[t1 + mrow + 8] = __float2bfloat16(v11 - __bfloat162float(h));
            }
        }
    }
}

// ---------------------------------------------------------------------------
// Flash attention via mma.sync bf16 hi/lo (3-pass), cp.async double-buffered.
// CTA: 128 q-rows x head, 256 threads = 8 warps, each warp 16 q-rows.
// ---------------------------------------------------------------------------
#define AQ_H   0
#define AQ_L   16384
#define ABUF0  32768
#define ABUF_SZ 32768
#define A_KH   0
#define A_KL   8192
#define A_VH   16384
#define A_VL   24576
#define ASMEM  (ABUF0 + 2 * ABUF_SZ)   // 98304

__device__ __forceinline__ void attn_stage_kv(uint32_t sbuf, int head, int kv0, int tid)
{
    #pragma unroll
    for (int i = 0; i < 2; i++) {
        int c = i * 256 + tid;               // 512 chunks per 8KB tile
        int row = c >> 3, col = c & 7;
        uint32_t off = SWZ((uint32_t)(row * 128 + col * 16));
        size_t gk = (size_t)(kv0 + row) * DIM + head * HD + col * 8;
        cp16(sbuf + A_KH + off, g_Kh + gk);
        cp16(sbuf + A_KL + off, g_Kl + gk);
        size_t gv = (size_t)(head * HD + row) * SEQ + kv0 + col * 8;
        cp16(sbuf + A_VH + off, g_Vth + gv);
        cp16(sbuf + A_VL + off, g_Vtl + gv);
    }
}

__global__ __launch_bounds__(256, 2) void attn_mma_kernel()
{
    extern __shared__ char smem[];
    const uint32_t sb = smem_to_u32(smem);
    const int tid  = threadIdx.x;
    const int w    = tid >> 5;
    const int l    = tid & 31;
    const int head = blockIdx.y;
    const int q0   = blockIdx.x * 128;

    const int qrow = (l & 7) + ((l >> 3) & 1) * 8;
    const int qkb  = ((l >> 4) & 1) * 16;
    const int bn   = (l & 7) + ((l >> 4) & 1) * 8;
    const int bkb  = ((l >> 3) & 1) * 16;

    // stage Q (128x64 hi/lo) via cp.async
    #pragma unroll
    for (int i = 0; i < 4; i++) {
        int c = i * 256 + tid;
        int row = c >> 3, col = c & 7;
        uint32_t off = SWZ((uint32_t)(row * 128 + col * 16));
        size_t gq = (size_t)(q0 + row) * DIM + head * HD + col * 8;
        cp16(sb + AQ_H + off, g_Qh + gq);
        cp16(sb + AQ_L + off, g_Ql + gq);
    }
    attn_stage_kv(sb + ABUF0, head, 0, tid);
    CP_COMMIT();

    float m0 = -1e30f, m1 = -1e30f;
    float l0 = 0.f, l1 = 0.f;
    float O[8][4];
    #pragma unroll
    for (int nt = 0; nt < 8; nt++)
        #pragma unroll
        for (int j = 0; j < 4; j++) O[nt][j] = 0.f;

    for (int it = 0; it < SEQ / 64; ++it) {
        if (it < SEQ / 64 - 1) {
            attn_stage_kv(sb + ABUF0 + ((it + 1) & 1) * ABUF_SZ, head, (it + 1) * 64, tid);
            CP_COMMIT();
            cp_wait<1>();
        } else {
            cp_wait<0>();
        }
        __syncthreads();

        const uint32_t buf = sb + ABUF0 + (it & 1) * ABUF_SZ;

        // ---- S = Q K^T (hi/lo 3-pass) ----
        float s[8][4];
        #pragma unroll
        for (int nt = 0; nt < 8; nt++)
            #pragma unroll
            for (int j = 0; j < 4; j++) s[nt][j] = 0.f;

        #pragma unroll
        for (int kt = 0; kt < 4; kt++) {
            uint32_t qoff = SWZ((uint32_t)((w * 16 + qrow) * 128 + kt * 32 + qkb));
            uint32_t qh0, qh1, qh2, qh3, ql0, ql1, ql2, ql3;
            ldsm_x4(sb + AQ_H + qoff, qh0, qh1, qh2, qh3);
            ldsm_x4(sb + AQ_L + qoff, ql0, ql1, ql2, ql3);
            #pragma unroll
            for (int ntp = 0; ntp < 4; ntp++) {
                uint32_t off = SWZ((uint32_t)((ntp * 16 + bn) * 128 + kt * 32 + bkb));
                uint32_t kh0, kh1, kh2, kh3, kl0, kl1, kl2, kl3;
                ldsm_x4(buf + A_KH + off, kh0, kh1, kh2, kh3);
                ldsm_x4(buf + A_KL + off, kl0, kl1, kl2, kl3);
                float* sa = s[2 * ntp];
                float* sc = s[2 * ntp + 1];
                // interleaved: alternate the two independent accumulators
                mma_bf16(sa[0], sa[1], sa[2], sa[3], qh0, qh1, qh2, qh3, kh0, kh1);
                mma_bf16(sc[0], sc[1], sc[2], sc[3], qh0, qh1, qh2, qh3, kh2, kh3);
                mma_bf16(sa[0], sa[1], sa[2], sa[3], ql0, ql1, ql2, ql3, kh0, kh1);
                mma_bf16(sc[0], sc[1], sc[2], sc[3], ql0, ql1, ql2, ql3, kh2, kh3);
                mma_bf16(sa[0], sa[1], sa[2], sa[3], qh0, qh1, qh2, qh3, kl0, kl1);
                mma_bf16(sc[0], sc[1], sc[2], sc[3], qh0, qh1, qh2, qh3, kl2, kl3);
            }
        }

        // ---- online softmax ----
        float mx0 = m0, mx1 = m1;
        #pragma unroll
        for (int nt = 0; nt < 8; nt++) {
            mx0 = fmaxf(mx0, fmaxf(s[nt][0], s[nt][1]));
            mx1 = fmaxf(mx1, fmaxf(s[nt][2], s[nt][3]));
        }
        mx0 = fmaxf(mx0, __shfl_xor_sync(0xffffffffu, mx0, 1));
        mx0 = fmaxf(mx0, __shfl_xor_sync(0xffffffffu, mx0, 2));
        mx1 = fmaxf(mx1, __shfl_xor_sync(0xffffffffu, mx1, 1));
        mx1 = fmaxf(mx1, __shfl_xor_sync(0xffffffffu, mx1, 2));
        const float alpha0 = __expf(m0 - mx0);
        const float alpha1 = __expf(m1 - mx1);
        m0 = mx0; m1 = mx1;

        uint32_t ph[4][4], pl[4][4];
        float rs0 = 0.f, rs1 = 0.f;
        #pragma unroll
        for (int nt = 0; nt < 8; nt++) {
            float p0 = __expf(s[nt][0] - mx0);
            float p1 = __expf(s[nt][1] - mx0);
            float p2 = __expf(s[nt][2] - mx1);
            float p3 = __expf(s[nt][3] - mx1);
            rs0 += p0 + p1; rs1 += p2 + p3;
            __nv_bfloat162 h01 = __floats2bfloat162_rn(p0, p1);
            __nv_bfloat162 h23 = __floats2bfloat162_rn(p2, p3);
            __nv_bfloat162 l01 = __floats2bfloat162_rn(p0 - __bfloat162float(h01.x),
                                                       p1 - __bfloat162float(h01.y));
            __nv_bfloat162 l23 = __floats2bfloat162_rn(p2 - __bfloat162float(h23.x),
                                                       p3 - __bfloat162float(h23.y));
            const int kt = nt >> 1, hi = (nt & 1) * 2;
            ph[kt][hi + 0] = *(uint32_t*)&h01;
            ph[kt][hi + 1] = *(uint32_t*)&h23;
            pl[kt][hi + 0] = *(uint32_t*)&l01;
            pl[kt][hi + 1] = *(uint32_t*)&l23;
        }
        l0 = l0 * alpha0 + rs0;
        l1 = l1 * alpha1 + rs1;

        #pragma unroll
        for (int nt = 0; nt < 8; nt++) {
            O[nt][0] *= alpha0; O[nt][1] *= alpha0;
            O[nt][2] *= alpha1; O[nt][3] *= alpha1;
        }

        // ---- O += P @ V (hi/lo 3-pass) ----
        #pragma unroll
        for (int ntp = 0; ntp < 4; ntp++) {
            #pragma unroll
            for (int kt = 0; kt < 4; kt++) {
                uint32_t off = SWZ((uint32_t)((ntp * 16 + bn) * 128 + kt * 32 + bkb));
                uint32_t vh0, vh1, vh2, vh3, vl0, vl1, vl2, vl3;
                ldsm_x4(buf + A_VH + off, vh0, vh1, vh2, vh3);
                ldsm_x4(buf + A_VL + off, vl0, vl1, vl2, vl3);
                float* oa = O[2 * ntp];
                float* oc = O[2 * ntp + 1];
                mma_bf16(oa[0], oa[1], oa[2], oa[3], ph[kt][0], ph[kt][1], ph[kt][2], ph[kt][3], vh0, vh1);
                mma_bf16(oc[0], oc[1], oc[2], oc[3], ph[kt][0], ph[kt][1], ph[kt][2], ph[kt][3], vh2, vh3);
                mma_bf16(oa[0], oa[1], oa[2], oa[3], pl[kt][0], pl[kt][1], pl[kt][2], pl[kt][3], vh0, vh1);
                mma_bf16(oc[0], oc[1], oc[2], oc[3], pl[kt][0], pl[kt][1], pl[kt][2], pl[kt][3], vh2, vh3);
                mma_bf16(oa[0], oa[1], oa[2], oa[3], ph[kt][0], ph[kt][1], ph[kt][2], ph[kt][3], vl0, vl1);
                mma_bf16(oc[0], oc[1], oc[2], oc[3], ph[kt][0], ph[kt][1], ph[kt][2], ph[kt][3], vl2, vl3);
            }
        }
        __syncthreads();   // all reads of buf done before it is restaged
    }

    l0 += __shfl_xor_sync(0xffffffffu, l0, 1);
    l0 += __shfl_xor_sync(0xffffffffu, l0, 2);
    l1 += __shfl_xor_sync(0xffffffffu, l1, 1);
    l1 += __shfl_xor_sync(0xffffffffu, l1, 2);
    const float inv0 = 1.f / l0, inv1 = 1.f / l1;
    const int r = l >> 2, cc = (l & 3) * 2;
    const size_t off0 = (size_t)(q0 + w * 16 + r)     * DIM + head * HD;
    const size_t off1 = (size_t)(q0 + w * 16 + r + 8) * DIM + head * HD;
    #pragma unroll
    for (int nt = 0; nt < 8; nt++) {
        float v00 = O[nt][0] * inv0, v01 = O[nt][1] * inv0;
        float v10 = O[nt][2] * inv1, v11 = O[nt][3] * inv1;
        __nv_bfloat162 h0 = __floats2bfloat162_rn(v00, v01);
        __nv_bfloat162 l0b = __floats2bfloat162_rn(v00 - __bfloat162float(h0.x),
                                                   v01 - __bfloat162float(h0.y));
        __nv_bfloat162 h1 = __floats2bfloat162_rn(v10, v11);
        __nv_bfloat162 l1b = __floats2bfloat162_rn(v10 - __bfloat162float(h1.x),
                                                   v11 - __bfloat162float(h1.y));
        *(__nv_bfloat162*)(g_ctxh + off0 + nt * 8 + cc) = h0;
        *(__nv_bfloat162*)(g_ctxl + off0 + nt * 8 + cc) = l0b;
        *(__nv_bfloat162*)(g_ctxh + off1 + nt * 8 + cc) = h1;
        *(__nv_bfloat162*)(g_ctxl + off1 + nt * 8 + cc) = l1b;
    }
}

// ---------------------------------------------------------------------------
extern "C" void kernel_launch(void* const* d_in, const int* in_sizes, int n_in,
                              void* d_out, int out_size)
{
    const float* x  = (const float*)d_in[0];
    const float* Wq = (const float*)d_in[1];
    const float* bq = (const float*)d_in[2];
    const float* Wk = (const float*)d_in[3];
    const float* bk = (const float*)d_in[4];
    const float* Wv = (const float*)d_in[5];
    const float* bv = (const float*)d_in[6];
    const float* Wo = (const float*)d_in[7];
    const float* bo = (const float*)d_in[8];
    float* out = (float*)d_out;

    __nv_bfloat16 *xh, *xl, *Wqh, *Wql, *Wkh, *Wkl, *Wvh, *Wvl, *Woh, *Wol;
    __nv_bfloat16 *Qh, *Ql, *Kh, *Kl, *ctxh, *ctxl;
    cudaGetSymbolAddress((void**)&xh,  g_xh);
    cudaGetSymbolAddress((void**)&xl,  g_xl);
    cudaGetSymbolAddress((void**)&Wqh, g_Wqh);
    cudaGetSymbolAddress((void**)&Wql, g_Wql);
    cudaGetSymbolAddress((void**)&Wkh, g_Wkh);
    cudaGetSymbolAddress((void**)&Wkl, g_Wkl);
    cudaGetSymbolAddress((void**)&Wvh, g_Wvh);
    cudaGetSymbolAddress((void**)&Wvl, g_Wvl);
    cudaGetSymbolAddress((void**)&Woh, g_Woh);
    cudaGetSymbolAddress((void**)&Wol, g_Wol);
    cudaGetSymbolAddress((void**)&Qh,  g_Qh);
    cudaGetSymbolAddress((void**)&Ql,  g_Ql);
    cudaGetSymbolAddress((void**)&Kh,  g_Kh);
    cudaGetSymbolAddress((void**)&Kl,  g_Kl);
    cudaGetSymbolAddress((void**)&ctxh, g_ctxh);
    cudaGetSymbolAddress((void**)&ctxl, g_ctxl);

    convert_all_kernel<<<1536, 256>>>(x, Wq, Wk, Wv, Wo);

    cudaFuncSetAttribute(gemm_tc_kernel,
                         cudaFuncAttributeMaxDynamicSharedMemorySize, GSMEM);
    dim3 ggrid(DIM / 64, SEQ / 128);   // (8, 32)

    gemm_tc_kernel<<<ggrid, 256, GSMEM>>>(xh, xl, Wqh, Wql, bq,
                                          nullptr, Qh, Ql, 0.125f, 1);
    gemm_tc_kernel<<<ggrid, 256, GSMEM>>>(xh, xl, Wkh, Wkl, bk,
                                          nullptr, Kh, Kl, 1.f, 1);
    gemm_tc_kernel<<<ggrid, 256, GSMEM>>>(xh, xl, Wvh, Wvl, bv,
                                          nullptr, nullptr, nullptr, 1.f, 2);

    cudaFuncSetAttribute(attn_mma_kernel,
                         cudaFuncAttributeMaxDynamicSharedMemorySize, ASMEM);
    attn_mma_kernel<<<dim3(SEQ / 128, NH), 256, ASMEM>>>();

    gemm_tc_kernel<<<ggrid, 256, GSMEM>>>(ctxh, ctxl, Woh, Wol, bo,
                                          out, nullptr, nullptr, 1.f, 0);
}

// round 7
// speedup vs baseline: 4.9346x; 1.0584x over previous
#include <cuda_runtime.h>
#include <cuda_bf16.h>
#include <math.h>
#include <cstdint>

// Problem constants
#define SEQ   4096
#define DIM   512
#define NH    8
#define HD    64

// 0.125 (1/sqrt(64)) * log2(e): folds softmax base-2 conversion into Q scale
#define QSCALE 0.18033688011112042f

// ---------------------------------------------------------------------------
// Scratch (allocation-free rule: __device__ globals)
// ---------------------------------------------------------------------------
__device__ __nv_bfloat16 g_xh[SEQ * DIM];
__device__ __nv_bfloat16 g_xl[SEQ * DIM];
__device__ __nv_bfloat16 g_Wqh[DIM * DIM], g_Wql[DIM * DIM];
__device__ __nv_bfloat16 g_Wkh[DIM * DIM], g_Wkl[DIM * DIM];
__device__ __nv_bfloat16 g_Wvh[DIM * DIM], g_Wvl[DIM * DIM];
__device__ __nv_bfloat16 g_Woh[DIM * DIM], g_Wol[DIM * DIM];

__device__ __nv_bfloat16 g_Qh[SEQ * DIM];
__device__ __nv_bfloat16 g_Ql[SEQ * DIM];
__device__ __nv_bfloat16 g_Kh[SEQ * DIM];
__device__ __nv_bfloat16 g_Kl[SEQ * DIM];
// V transposed per head: [head][hd=64][seq=4096]
__device__ __nv_bfloat16 g_Vth[NH * HD * SEQ];
__device__ __nv_bfloat16 g_Vtl[NH * HD * SEQ];
// attention output, bf16 hi/lo split (feeds final GEMM)
__device__ __nv_bfloat16 g_ctxh[SEQ * DIM];
__device__ __nv_bfloat16 g_ctxl[SEQ * DIM];

// ---------------------------------------------------------------------------
// helpers (baseline PTX: sm_80 mma.sync + sm_75 ldmatrix + cp.async)
// ---------------------------------------------------------------------------
__device__ __forceinline__ uint32_t smem_to_u32(const void* p) {
    uint32_t a;
    asm("{ .reg .u64 t; cvta.to.shared.u64 t, %1; cvt.u32.u64 %0, t; }"
        : "=r"(a) : "l"(p));
    return a;
}

__device__ __forceinline__ float ex2(float x) {
    float y;
    asm("ex2.approx.f32 %0, %1;" : "=f"(y) : "f"(x));
    return y;
}

#define SWZ(b) ((b) ^ (((b) >> 3) & 0x70))

__device__ __forceinline__ void ldsm_x4(uint32_t addr, uint32_t& r0, uint32_t& r1,
                                        uint32_t& r2, uint32_t& r3) {
    asm volatile("ldmatrix.sync.aligned.m8n8.x4.shared.b16 {%0,%1,%2,%3}, [%4];"
                 : "=r"(r0), "=r"(r1), "=r"(r2), "=r"(r3) : "r"(addr));
}

__device__ __forceinline__ void mma_bf16(float& d0, float& d1, float& d2, float& d3,
                                         uint32_t a0, uint32_t a1, uint32_t a2, uint32_t a3,
                                         uint32_t b0, uint32_t b1) {
    asm("mma.sync.aligned.m16n8k16.row.col.f32.bf16.bf16.f32 "
        "{%0,%1,%2,%3}, {%4,%5,%6,%7}, {%8,%9}, {%0,%1,%2,%3};"
        : "+f"(d0), "+f"(d1), "+f"(d2), "+f"(d3)
        : "r"(a0), "r"(a1), "r"(a2), "r"(a3), "r"(b0), "r"(b1));
}

__device__ __forceinline__ void cp16(uint32_t dst, const void* src) {
    asm volatile("cp.async.cg.shared.global [%0], [%1], 16;" :: "r"(dst), "l"(src));
}
#define CP_COMMIT() asm volatile("cp.async.commit_group;" ::: "memory")
template <int N>
__device__ __forceinline__ void cp_wait() {
    asm volatile("cp.async.wait_group %0;" :: "n"(N) : "memory");
}

// ---------------------------------------------------------------------------
// Fused fp32 -> bf16 hi/lo conversion for x + all 4 weights (one launch)
// ---------------------------------------------------------------------------
#define NX (SEQ * DIM)
#define NW (DIM * DIM)
__global__ void convert_all_kernel(const float* __restrict__ x,
                                   const float* __restrict__ Wq,
                                   const float* __restrict__ Wk,
                                   const float* __restrict__ Wv,
                                   const float* __restrict__ Wo)
{
    const int total4 = (NX + 4 * NW) / 4;
    int i4 = blockIdx.x * blockDim.x + threadIdx.x;
    const int stride = gridDim.x * blockDim.x;
    for (; i4 < total4; i4 += stride) {
        int idx = i4 * 4;
        const float* src;
        __nv_bfloat16 *dh, *dl;
        int off;
        if (idx < NX)                { src = x;  dh = g_xh;  dl = g_xl;  off = idx; }
        else if (idx < NX + NW)      { src = Wq; dh = g_Wqh; dl = g_Wql; off = idx - NX; }
        else if (idx < NX + 2 * NW)  { src = Wk; dh = g_Wkh; dl = g_Wkl; off = idx - NX - NW; }
        else if (idx < NX + 3 * NW)  { src = Wv; dh = g_Wvh; dl = g_Wvl; off = idx - NX - 2 * NW; }
        else                         { src = Wo; dh = g_Woh; dl = g_Wol; off = idx - NX - 3 * NW; }
        float4 v = *(const float4*)(src + off);
        __nv_bfloat162 h01 = __floats2bfloat162_rn(v.x, v.y);
        __nv_bfloat162 h23 = __floats2bfloat162_rn(v.z, v.w);
        __nv_bfloat162 l01 = __floats2bfloat162_rn(v.x - __bfloat162float(h01.x),
                                                   v.y - __bfloat162float(h01.y));
        __nv_bfloat162 l23 = __floats2bfloat162_rn(v.z - __bfloat162float(h23.x),
                                                   v.w - __bfloat162float(h23.y));
        *(__nv_bfloat162*)(dh + off)     = h01;
        *(__nv_bfloat162*)(dh + off + 2) = h23;
        *(__nv_bfloat162*)(dl + off)     = l01;
        *(__nv_bfloat162*)(dl + off + 2) = l23;
    }
}

// ---------------------------------------------------------------------------
// GEMM tiling constants (shared by the two GEMM kernels)
// CTA tile 128M x 64N, warps 4(M) x 2(N), warp tile 32x32, cp.async dbl-buffer.
// ---------------------------------------------------------------------------
#define GOFF_AH 0
#define GOFF_AL 16384
#define GOFF_BH 32768
#define GOFF_BL 40960
#define GBUF    49152
#define GSMEM   (2 * GBUF)   // 98304

__device__ __forceinline__ void gemm_stage_chunk(
    uint32_t sbuf,
    const __nv_bfloat16* __restrict__ Ah, const __nv_bfloat16* __restrict__ Al,
    const __nv_bfloat16* __restrict__ Bh, const __nv_bfloat16* __restrict__ Bl,
    int m0, int n0, int k0, int tid)
{
    #pragma unroll
    for (int i = 0; i < 4; i++) {                  // A: 128 rows x 64 cols
        int c = i * 256 + tid;
        int row = c >> 3, col = c & 7;
        uint32_t off = SWZ((uint32_t)(row * 128 + col * 16));
        size_t gidx = (size_t)(m0 + row) * DIM + k0 + col * 8;
        cp16(sbuf + GOFF_AH + off, Ah + gidx);
        cp16(sbuf + GOFF_AL + off, Al + gidx);
    }
    #pragma unroll
    for (int i = 0; i < 2; i++) {                  // B: 64 rows x 64 cols
        int c = i * 256 + tid;
        int row = c >> 3, col = c & 7;
        uint32_t off = SWZ((uint32_t)(row * 128 + col * 16));
        size_t gidx = (size_t)(n0 + row) * DIM + k0 + col * 8;
        cp16(sbuf + GOFF_BH + off, Bh + gidx);
        cp16(sbuf + GOFF_BL + off, Bl + gidx);
    }
}

// main-loop body shared textually by both GEMM kernels
#define GEMM_MAINLOOP(Ah, Al, Bh, Bl)                                          \
    gemm_stage_chunk(sb, Ah, Al, Bh, Bl, m0, n0, 0, tid);                      \
    CP_COMMIT();                                                               \
    for (int ch = 0; ch < 8; ch++) {                                           \
        if (ch < 7) {                                                          \
            gemm_stage_chunk(sb + ((ch + 1) & 1) * GBUF, Ah, Al, Bh, Bl,       \
                             m0, n0, (ch + 1) * 64, tid);                      \
            CP_COMMIT();                                                       \
            cp_wait<1>();                                                      \
        } else {                                                               \
            cp_wait<0>();                                                      \
        }                                                                      \
        __syncthreads();                                                       \
        const uint32_t b = sb + (ch & 1) * GBUF;                               \
        _Pragma("unroll")                                                      \
        for (int kt = 0; kt < 4; kt++) {                                       \
            uint32_t ah[2][4], al[2][4];                                       \
            _Pragma("unroll")                                                  \
            for (int mf = 0; mf < 2; mf++) {                                   \
                uint32_t aoff = SWZ((uint32_t)((wm*32 + mf*16 + qrow)*128 + kt*32 + qkb)); \
                ldsm_x4(b + GOFF_AH + aoff, ah[mf][0], ah[mf][1], ah[mf][2], ah[mf][3]); \
                ldsm_x4(b + GOFF_AL + aoff, al[mf][0], al[mf][1], al[mf][2], al[mf][3]); \
            }                                                                  \
            _Pragma("unroll")                                                  \
            for (int np = 0; np < 2; np++) {                                   \
                uint32_t boff = SWZ((uint32_t)((wn*32 + np*16 + bn)*128 + kt*32 + bkb)); \
                uint32_t bh0, bh1, bh2, bh3, bl0, bl1, bl2, bl3;               \
                ldsm_x4(b + GOFF_BH + boff, bh0, bh1, bh2, bh3);               \
                ldsm_x4(b + GOFF_BL + boff, bl0, bl1, bl2, bl3);               \
                _Pragma("unroll")                                              \
                for (int mf = 0; mf < 2; mf++) {                               \
                    float* a0 = acc[mf][2 * np];                               \
                    float* a1 = acc[mf][2 * np + 1];                           \
                    mma_bf16(a0[0],a0[1],a0[2],a0[3], ah[mf][0],ah[mf][1],ah[mf][2],ah[mf][3], bh0,bh1); \
                    mma_bf16(a1[0],a1[1],a1[2],a1[3], ah[mf][0],ah[mf][1],ah[mf][2],ah[mf][3], bh2,bh3); \
                    mma_bf16(a0[0],a0[1],a0[2],a0[3], al[mf][0],al[mf][1],al[mf][2],al[mf][3], bh0,bh1); \
                    mma_bf16(a1[0],a1[1],a1[2],a1[3], al[mf][0],al[mf][1],al[mf][2],al[mf][3], bh2,bh3); \
                    mma_bf16(a0[0],a0[1],a0[2],a0[3], ah[mf][0],ah[mf][1],ah[mf][2],ah[mf][3], bl0,bl1); \
                    mma_bf16(a1[0],a1[1],a1[2],a1[3], ah[mf][0],ah[mf][1],ah[mf][2],ah[mf][3], bl2,bl3); \
                }                                                              \
            }                                                                  \
        }                                                                      \
        __syncthreads();                                                       \
    }

// ---------------------------------------------------------------------------
// Fused Q/K/V projection GEMM: blockIdx.z selects weights/bias/epilogue.
//   z=0: Q -> bf16 hi/lo, scale = QSCALE (0.125*log2e folded for exp2 softmax)
//   z=1: K -> bf16 hi/lo
//   z=2: V -> transposed per-head hi/lo [head][hd][seq]
// ---------------------------------------------------------------------------
__global__ __launch_bounds__(256, 2) void gemm_qkv_kernel(
    const float* __restrict__ bq, const float* __restrict__ bk,
    const float* __restrict__ bv)
{
    extern __shared__ char smem[];
    const uint32_t sb = smem_to_u32(smem);
    const int tid = threadIdx.x;
    const int w   = tid >> 5;
    const int l   = tid & 31;
    const int wm  = w & 3;
    const int wn  = w >> 2;
    const int m0  = blockIdx.y * 128;
    const int n0  = blockIdx.x * 64;
    const int z   = blockIdx.z;

    const __nv_bfloat16 *Bh, *Bl;
    const float* bias;
    float scale;
    if (z == 0)      { Bh = g_Wqh; Bl = g_Wql; bias = bq; scale = QSCALE; }
    else if (z == 1) { Bh = g_Wkh; Bl = g_Wkl; bias = bk; scale = 1.f; }
    else             { Bh = g_Wvh; Bl = g_Wvl; bias = bv; scale = 1.f; }

    const int qrow = (l & 7) + ((l >> 3) & 1) * 8;
    const int qkb  = ((l >> 4) & 1) * 16;
    const int bn   = (l & 7) + ((l >> 4) & 1) * 8;
    const int bkb  = ((l >> 3) & 1) * 16;

    float acc[2][4][4];
    #pragma unroll
    for (int mf = 0; mf < 2; mf++)
        #pragma unroll
        for (int j = 0; j < 4; j++)
            #pragma unroll
            for (int q = 0; q < 4; q++) acc[mf][j][q] = 0.f;

    GEMM_MAINLOOP(g_xh, g_xl, Bh, Bl)

    const int r = l >> 2, cc = (l & 3) * 2;
    #pragma unroll
    for (int mf = 0; mf < 2; mf++) {
        const int mrow = m0 + wm * 32 + mf * 16 + r;
        #pragma unroll
        for (int j = 0; j < 4; j++) {
            const int col = n0 + wn * 32 + (j >> 1) * 16 + (j & 1) * 8 + cc;
            const float b0 = bias[col], b1 = bias[col + 1];
            float v00 = (acc[mf][j][0] + b0) * scale;
            float v01 = (acc[mf][j][1] + b1) * scale;
            float v10 = (acc[mf][j][2] + b0) * scale;
            float v11 = (acc[mf][j][3] + b1) * scale;
            if (z < 2) {
                __nv_bfloat16* Ch = (z == 0) ? g_Qh : g_Kh;
                __nv_bfloat16* Cl = (z == 0) ? g_Ql : g_Kl;
                __nv_bfloat162 h0 = __floats2bfloat162_rn(v00, v01);
                __nv_bfloat162 l0 = __floats2bfloat162_rn(v00 - __bfloat162float(h0.x),
                                                          v01 - __bfloat162float(h0.y));
                __nv_bfloat162 h1 = __floats2bfloat162_rn(v10, v11);
                __nv_bfloat162 l1 = __floats2bfloat162_rn(v10 - __bfloat162float(h1.x),
                                                          v11 - __bfloat162float(h1.y));
                *(__nv_bfloat162*)&Ch[(size_t)mrow * DIM + col]       = h0;
                *(__nv_bfloat162*)&Cl[(size_t)mrow * DIM + col]       = l0;
                *(__nv_bfloat162*)&Ch[(size_t)(mrow + 8) * DIM + col] = h1;
                *(__nv_bfloat162*)&Cl[(size_t)(mrow + 8) * DIM + col] = l1;
            } else {
                const int head = col >> 6, hd = col & 63;
                const size_t t0 = (size_t)(head * HD + hd)     * SEQ;
                const size_t t1 = (size_t)(head * HD + hd + 1) * SEQ;
                __nv_bfloat16 h;
                h = __float2bfloat16(v00);
                g_Vth[t0 + mrow] = h; g_Vtl[t0 + mrow] = __float2bfloat16(v00 - __bfloat162float(h));
                h = __float2bfloat16(v01);
                g_Vth[t1 + mrow] = h; g_Vtl[t1 + mrow] = __float2bfloat16(v01 - __bfloat162float(h));
                h = __float2bfloat16(v10);
                g_Vth[t0 + mrow + 8] = h; g_Vtl[t0 + mrow + 8] = __float2bfloat16(v10 - __bfloat162float(h));
                h = __float2bfloat16(v11);
                g_Vth[t1 + mrow + 8] = h; g_Vtl[t1 + mrow + 8] = __float2bfloat16(v11 - __bfloat162float(h));
            }
        }
    }
}

// ---------------------------------------------------------------------------
// Output projection GEMM: out = ctx @ Wo^T + bo (fp32 epilogue)
// ---------------------------------------------------------------------------
__global__ __launch_bounds__(256, 2) void gemm_out_kernel(
    const float* __restrict__ bias, float* __restrict__ Cf)
{
    extern __shared__ char smem[];
    const uint32_t sb = smem_to_u32(smem);
    const int tid = threadIdx.x;
    const int w   = tid >> 5;
    const int l   = tid & 31;
    const int wm  = w & 3;
    const int wn  = w >> 2;
    const int m0  = blockIdx.y * 128;
    const int n0  = blockIdx.x * 64;

    const int qrow = (l & 7) + ((l >> 3) & 1) * 8;
    const int qkb  = ((l >> 4) & 1) * 16;
    const int bn   = (l & 7) + ((l >> 4) & 1) * 8;
    const int bkb  = ((l >> 3) & 1) * 16;

    float acc[2][4][4];
    #pragma unroll
    for (int mf = 0; mf < 2; mf++)
        #pragma unroll
        for (int j = 0; j < 4; j++)
            #pragma unroll
            for (int q = 0; q < 4; q++) acc[mf][j][q] = 0.f;

    GEMM_MAINLOOP(g_ctxh, g_ctxl, g_Woh, g_Wol)

    const int r = l >> 2, cc = (l & 3) * 2;
    #pragma unroll
    for (int mf = 0; mf < 2; mf++) {
        const int mrow = m0 + wm * 32 + mf * 16 + r;
        #pragma unroll
        for (int j = 0; j < 4; j++) {
            const int col = n0 + wn * 32 + (j >> 1) * 16 + (j & 1) * 8 + cc;
            const float b0 = bias[col], b1 = bias[col + 1];
            *(float2*)&Cf[(size_t)mrow * DIM + col] =
                make_float2(acc[mf][j][0] + b0, acc[mf][j][1] + b1);
            *(float2*)&Cf[(size_t)(mrow + 8) * DIM + col] =
                make_float2(acc[mf][j][2] + b0, acc[mf][j][3] + b1);
        }
    }
}

// ---------------------------------------------------------------------------
// Flash attention via mma.sync bf16 hi/lo (3-pass), cp.async double-buffered.
// Softmax exp/pack is interleaved with PV MMAs (kt-granularity) so MUFU work
// overlaps tensor work. exp2 domain (log2e folded into Q scale).
// ---------------------------------------------------------------------------
#define AQ_H   0
#define AQ_L   16384
#define ABUF0  32768
#define ABUF_SZ 32768
#define A_KH   0
#define A_KL   8192
#define A_VH   16384
#define A_VL   24576
#define ASMEM  (ABUF0 + 2 * ABUF_SZ)   // 98304

__device__ __forceinline__ void attn_stage_kv(uint32_t sbuf, int head, int kv0, int tid)
{
    #pragma unroll
    for (int i = 0; i < 2; i++) {
        int c = i * 256 + tid;               // 512 chunks per 8KB tile
        int row = c >> 3, col = c & 7;
        uint32_t off = SWZ((uint32_t)(row * 128 + col * 16));
        size_t gk = (size_t)(kv0 + row) * DIM + head * HD + col * 8;
        cp16(sbuf + A_KH + off, g_Kh + gk);
        cp16(sbuf + A_KL + off, g_Kl + gk);
        size_t gv = (size_t)(head * HD + row) * SEQ + kv0 + col * 8;
        cp16(sbuf + A_VH + off, g_Vth + gv);
        cp16(sbuf + A_VL + off, g_Vtl + gv);
    }
}

__global__ __launch_bounds__(256, 2) void attn_mma_kernel()
{
    extern __shared__ char smem[];
    const uint32_t sb = smem_to_u32(smem);
    const int tid  = threadIdx.x;
    const int w    = tid >> 5;
    const int l    = tid & 31;
    const int head = blockIdx.y;
    const int q0   = blockIdx.x * 128;

    const int qrow = (l & 7) + ((l >> 3) & 1) * 8;
    const int qkb  = ((l >> 4) & 1) * 16;
    const int bn   = (l & 7) + ((l >> 4) & 1) * 8;
    const int bkb  = ((l >> 3) & 1) * 16;

    // stage Q (128x64 hi/lo) via cp.async
    #pragma unroll
    for (int i = 0; i < 4; i++) {
        int c = i * 256 + tid;
        int row = c >> 3, col = c & 7;
        uint32_t off = SWZ((uint32_t)(row * 128 + col * 16));
        size_t gq = (size_t)(q0 + row) * DIM + head * HD + col * 8;
        cp16(sb + AQ_H + off, g_Qh + gq);
        cp16(sb + AQ_L + off, g_Ql + gq);
    }
    attn_stage_kv(sb + ABUF0, head, 0, tid);
    CP_COMMIT();

    float m0 = -1e30f, m1 = -1e30f;
    float lr0 = 0.f, lr1 = 0.f;
    float O[8][4];
    #pragma unroll
    for (int nt = 0; nt < 8; nt++)
        #pragma unroll
        for (int j = 0; j < 4; j++) O[nt][j] = 0.f;

    for (int it = 0; it < SEQ / 64; ++it) {
        if (it < SEQ / 64 - 1) {
            attn_stage_kv(sb + ABUF0 + ((it + 1) & 1) * ABUF_SZ, head, (it + 1) * 64, tid);
            CP_COMMIT();
            cp_wait<1>();
        } else {
            cp_wait<0>();
        }
        __syncthreads();

        const uint32_t buf = sb + ABUF0 + (it & 1) * ABUF_SZ;

        // ---- S = Q K^T (hi/lo 3-pass), exp2 domain ----
        float s[8][4];
        #pragma unroll
        for (int nt = 0; nt < 8; nt++)
            #pragma unroll
            for (int j = 0; j < 4; j++) s[nt][j] = 0.f;

        #pragma unroll
        for (int kt = 0; kt < 4; kt++) {
            uint32_t qoff = SWZ((uint32_t)((w * 16 + qrow) * 128 + kt * 32 + qkb));
            uint32_t qh0, qh1, qh2, qh3, ql0, ql1, ql2, ql3;
            ldsm_x4(sb + AQ_H + qoff, qh0, qh1, qh2, qh3);
            ldsm_x4(sb + AQ_L + qoff, ql0, ql1, ql2, ql3);
            #pragma unroll
            for (int ntp = 0; ntp < 4; ntp++) {
                uint32_t off = SWZ((uint32_t)((ntp * 16 + bn) * 128 + kt * 32 + bkb));
                uint32_t kh0, kh1, kh2, kh3, kl0, kl1, kl2, kl3;
                ldsm_x4(buf + A_KH + off, kh0, kh1, kh2, kh3);
                ldsm_x4(buf + A_KL + off, kl0, kl1, kl2, kl3);
                float* sa = s[2 * ntp];
                float* sc = s[2 * ntp + 1];
                mma_bf16(sa[0], sa[1], sa[2], sa[3], qh0, qh1, qh2, qh3, kh0, kh1);
                mma_bf16(sc[0], sc[1], sc[2], sc[3], qh0, qh1, qh2, qh3, kh2, kh3);
                mma_bf16(sa[0], sa[1], sa[2], sa[3], ql0, ql1, ql2, ql3, kh0, kh1);
                mma_bf16(sc[0], sc[1], sc[2], sc[3], ql0, ql1, ql2, ql3, kh2, kh3);
                mma_bf16(sa[0], sa[1], sa[2], sa[3], qh0, qh1, qh2, qh3, kl0, kl1);
                mma_bf16(sc[0], sc[1], sc[2], sc[3], qh0, qh1, qh2, qh3, kl2, kl3);
            }
        }

        // ---- row max + alpha (serial part of online softmax) ----
        float mx0 = m0, mx1 = m1;
        #pragma unroll
        for (int nt = 0; nt < 8; nt++) {
            mx0 = fmaxf(mx0, fmaxf(s[nt][0], s[nt][1]));
            mx1 = fmaxf(mx1, fmaxf(s[nt][2], s[nt][3]));
        }
        mx0 = fmaxf(mx0, __shfl_xor_sync(0xffffffffu, mx0, 1));
        mx0 = fmaxf(mx0, __shfl_xor_sync(0xffffffffu, mx0, 2));
        mx1 = fmaxf(mx1, __shfl_xor_sync(0xffffffffu, mx1, 1));
        mx1 = fmaxf(mx1, __shfl_xor_sync(0xffffffffu, mx1, 2));
        const float alpha0 = ex2(m0 - mx0);
        const float alpha1 = ex2(m1 - mx1);
        m0 = mx0; m1 = mx1;
        lr0 *= alpha0; lr1 *= alpha1;
        #pragma unroll
        for (int nt = 0; nt < 8; nt++) {
            O[nt][0] *= alpha0; O[nt][1] *= alpha0;
            O[nt][2] *= alpha1; O[nt][3] *= alpha1;
        }

        // ---- interleaved: exp/pack k-tile kt, then its PV MMAs ----
        float rs0 = 0.f, rs1 = 0.f;
        #pragma unroll
        for (int kt = 0; kt < 4; kt++) {
            uint32_t ph4[4], pl4[4];
            #pragma unroll
            for (int h = 0; h < 2; h++) {
                const int nt = 2 * kt + h;
                float p0 = ex2(s[nt][0] - mx0);
                float p1 = ex2(s[nt][1] - mx0);
                float p2 = ex2(s[nt][2] - mx1);
                float p3 = ex2(s[nt][3] - mx1);
                rs0 += p0 + p1; rs1 += p2 + p3;
                __nv_bfloat162 h01 = __floats2bfloat162_rn(p0, p1);
                __nv_bfloat162 h23 = __floats2bfloat162_rn(p2, p3);
                __nv_bfloat162 lo01 = __floats2bfloat162_rn(p0 - __bfloat162float(h01.x),
                                                            p1 - __bfloat162float(h01.y));
                __nv_bfloat162 lo23 = __floats2bfloat162_rn(p2 - __bfloat162float(h23.x),
                                                            p3 - __bfloat162float(h23.y));
                ph4[2 * h + 0] = *(uint32_t*)&h01;
                ph4[2 * h + 1] = *(uint32_t*)&h23;
                pl4[2 * h + 0] = *(uint32_t*)&lo01;
                pl4[2 * h + 1] = *(uint32_t*)&lo23;
            }
            #pragma unroll
            for (int ntp = 0; ntp < 4; ntp++) {
                uint32_t off = SWZ((uint32_t)((ntp * 16 + bn) * 128 + kt * 32 + bkb));
                uint32_t vh0, vh1, vh2, vh3, vl0, vl1, vl2, vl3;
                ldsm_x4(buf + A_VH + off, vh0, vh1, vh2, vh3);
                ldsm_x4(buf + A_VL + off, vl0, vl1, vl2, vl3);
                float* oa = O[2 * ntp];
                float* oc = O[2 * ntp + 1];
                mma_bf16(oa[0], oa[1], oa[2], oa[3], ph4[0], ph4[1], ph4[2], ph4[3], vh0, vh1);
                mma_bf16(oc[0], oc[1], oc[2], oc[3], ph4[0], ph4[1], ph4[2], ph4[3], vh2, vh3);
                mma_bf16(oa[0], oa[1], oa[2], oa[3], pl4[0], pl4[1], pl4[2], pl4[3], vh0, vh1);
                mma_bf16(oc[0], oc[1], oc[2], oc[3], pl4[0], pl4[1], pl4[2], pl4[3], vh2, vh3);
                mma_bf16(oa[0], oa[1], oa[2], oa[3], ph4[0], ph4[1], ph4[2], ph4[3], vl0, vl1);
                mma_bf16(oc[0], oc[1], oc[2], oc[3], ph4[0], ph4[1], ph4[2], ph4[3], vl2, vl3);
            }
        }
        lr0 += rs0; lr1 += rs1;
        __syncthreads();   // all reads of buf done before it is restaged
    }

    lr0 += __shfl_xor_sync(0xffffffffu, lr0, 1);
    lr0 += __shfl_xor_sync(0xffffffffu, lr0, 2);
    lr1 += __shfl_xor_sync(0xffffffffu, lr1, 1);
    lr1 += __shfl_xor_sync(0xffffffffu, lr1, 2);
    const float inv0 = 1.f / lr0, inv1 = 1.f / lr1;
    const int r = l >> 2, cc = (l & 3) * 2;
    const size_t off0 = (size_t)(q0 + w * 16 + r)     * DIM + head * HD;
    const size_t off1 = (size_t)(q0 + w * 16 + r + 8) * DIM + head * HD;
    #pragma unroll
    for (int nt = 0; nt < 8; nt++) {
        float v00 = O[nt][0] * inv0, v01 = O[nt][1] * inv0;
        float v10 = O[nt][2] * inv1, v11 = O[nt][3] * inv1;
        __nv_bfloat162 h0 = __floats2bfloat162_rn(v00, v01);
        __nv_bfloat162 l0b = __floats2bfloat162_rn(v00 - __bfloat162float(h0.x),
                                                   v01 - __bfloat162float(h0.y));
        __nv_bfloat162 h1 = __floats2bfloat162_rn(v10, v11);
        __nv_bfloat162 l1b = __floats2bfloat162_rn(v10 - __bfloat162float(h1.x),
                                                   v11 - __bfloat162float(h1.y));
        *(__nv_bfloat162*)(g_ctxh + off0 + nt * 8 + cc) = h0;
        *(__nv_bfloat162*)(g_ctxl + off0 + nt * 8 + cc) = l0b;
        *(__nv_bfloat162*)(g_ctxh + off1 + nt * 8 + cc) = h1;
        *(__nv_bfloat162*)(g_ctxl + off1 + nt * 8 + cc) = l1b;
    }
}

// ---------------------------------------------------------------------------
extern "C" void kernel_launch(void* const* d_in, const int* in_sizes, int n_in,
                              void* d_out, int out_size)
{
    const float* x  = (const float*)d_in[0];
    const float* Wq = (const float*)d_in[1];
    const float* bq = (const float*)d_in[2];
    const float* Wk = (const float*)d_in[3];
    const float* bk = (const float*)d_in[4];
    const float* Wv = (const float*)d_in[5];
    const float* bv = (const float*)d_in[6];
    const float* Wo = (const float*)d_in[7];
    const float* bo = (const float*)d_in[8];
    float* out = (float*)d_out;

    convert_all_kernel<<<1536, 256>>>(x, Wq, Wk, Wv, Wo);

    cudaFuncSetAttribute(gemm_qkv_kernel,
                         cudaFuncAttributeMaxDynamicSharedMemorySize, GSMEM);
    cudaFuncSetAttribute(gemm_out_kernel,
                         cudaFuncAttributeMaxDynamicSharedMemorySize, GSMEM);

    gemm_qkv_kernel<<<dim3(DIM / 64, SEQ / 128, 3), 256, GSMEM>>>(bq, bk, bv);

    cudaFuncSetAttribute(attn_mma_kernel,
                         cudaFuncAttributeMaxDynamicSharedMemorySize, ASMEM);
    attn_mma_kernel<<<dim3(SEQ / 128, NH), 256, ASMEM>>>();

    gemm_out_kernel<<<dim3(DIM / 64, SEQ / 128), 256, GSMEM>>>(bo, out);
}